// round 12
// baseline (speedup 1.0000x reference)
#include <cuda_runtime.h>
#include <cuda_fp16.h>
#include <cstdint>
#include <math.h>

typedef unsigned long long ull;

// ---- static problem config ----
#define Nn    10000
#define NTOTc 80000
#define Bg    8
#define Emax  320000
#define Kk    30
#define ZLEN  3841           // K*C + 1
#define SBLK  547            // static-path tiles: ceil(70000/128)

// ---- scratch ----
__device__ float  g_q[Nn * 512];
__device__ __half g_kh[Nn * 512];
__device__ __half g_vh[Nn * 512];
__device__ float  g_hA[(size_t)NTOTc * 128];
__device__ float  g_hB[(size_t)NTOTc * 128];
__device__ int    g_deg[Nn + 1];
__device__ int    g_off[Nn + 1];
__device__ int    g_cur[Nn];
__device__ int    g_srcs[Emax];
__device__ ull    g_cand[80 * Kk];
__device__ float  g_z[Bg * ZLEN];
__device__ int    g_topk[Bg * Kk];

// ---- packed f32x2 helpers ----
static __device__ __forceinline__ ull pack2(float lo, float hi) {
    ull d; asm("mov.b64 %0, {%1, %2};" : "=l"(d) : "f"(lo), "f"(hi)); return d;
}
static __device__ __forceinline__ ull fma2(ull a, ull b, ull c) {
    ull d; asm("fma.rn.f32x2 %0, %1, %2, %3;" : "=l"(d) : "l"(a), "l"(b), "l"(c)); return d;
}
static __device__ __forceinline__ float2 unpack2(ull d) {
    float2 f; asm("mov.b64 {%0, %1}, %2;" : "=f"(f.x), "=f"(f.y) : "l"(d)); return f;
}

// ================= CSR build =================
__global__ void zero_deg_kernel() {
    int i = blockIdx.x * blockDim.x + threadIdx.x;
    if (i <= Nn) g_deg[i] = 0;
}
__global__ void hist_kernel(const int* __restrict__ dst, int E) {
    int e = blockIdx.x * blockDim.x + threadIdx.x;
    if (e < E) atomicAdd(&g_deg[dst[e]], 1);
}
__global__ __launch_bounds__(1024) void scan_kernel() {
    __shared__ int partial[1024];
    const int PER = 10;
    int t = threadIdx.x;
    int base = t * PER;
    int local[PER];
    int s = 0;
    #pragma unroll
    for (int i = 0; i < PER; i++) {
        int idx = base + i;
        int dv = (idx < Nn) ? g_deg[idx] : 0;
        local[i] = s; s += dv;
    }
    partial[t] = s;
    __syncthreads();
    for (int offd = 1; offd < 1024; offd <<= 1) {
        int addv = 0;
        if (t >= offd) addv = partial[t - offd];
        __syncthreads();
        if (t >= offd) partial[t] += addv;
        __syncthreads();
    }
    int pre = (t > 0) ? partial[t - 1] : 0;
    #pragma unroll
    for (int i = 0; i < PER; i++) {
        int idx = base + i;
        if (idx < Nn) { int o = pre + local[i]; g_off[idx] = o; g_cur[idx] = o; }
    }
    if (t == 1023) g_off[Nn] = partial[1023];
}
__global__ void scatter_kernel(const int* __restrict__ src,
                               const int* __restrict__ dst, int E) {
    int e = blockIdx.x * blockDim.x + threadIdx.x;
    if (e < E) {
        int d = dst[e];
        int p = atomicAdd(&g_cur[d], 1);
        g_srcs[p] = src[e];
    }
}

// ================= f32x2 GEMM core (R7 layout + prefetch + row clamp) =================
static __device__ __forceinline__ void gemm_core(
    const float* __restrict__ A, const float* __restrict__ W,
    int row0, int col0, int Nout, int Mtot, ull* acc,
    float (*As)[132], float (*Bs)[132])
{
    int tid = threadIdx.x;
    int tx = tid & 15;
    int ty = tid >> 4;

    #pragma unroll
    for (int i = 0; i < 32; i++) acc[i] = 0ull;

    int rA[2], kqA[2];
    float4 pa[2], pb[2];
    #pragma unroll
    for (int i = 0; i < 2; i++) {
        int f = tid + i * 256;
        int rr = row0 + (f >> 2);
        rA[i] = (rr < Mtot) ? rr : (Mtot - 1);   // clamp (stores guarded later)
        kqA[i] = (f & 3) * 4;
        pa[i] = *(const float4*)(A + (size_t)rA[i] * 128 + kqA[i]);
    }
    int kB = tid >> 4;
    int nB = (tid & 15) * 8;
    pb[0] = *(const float4*)(W + (size_t)kB * Nout + col0 + nB);
    pb[1] = *(const float4*)(W + (size_t)kB * Nout + col0 + nB + 4);

    int sr[2] = { (tid) >> 2, (tid + 256) >> 2 };

    for (int kc = 0; kc < 8; kc++) {
        __syncthreads();
        #pragma unroll
        for (int i = 0; i < 2; i++) {
            As[kqA[i] + 0][sr[i]] = pa[i].x;
            As[kqA[i] + 1][sr[i]] = pa[i].y;
            As[kqA[i] + 2][sr[i]] = pa[i].z;
            As[kqA[i] + 3][sr[i]] = pa[i].w;
        }
        *(float4*)&Bs[kB][nB]     = pb[0];
        *(float4*)&Bs[kB][nB + 4] = pb[1];
        __syncthreads();
        if (kc < 7) {
            int k0n = (kc + 1) * 16;
            #pragma unroll
            for (int i = 0; i < 2; i++)
                pa[i] = *(const float4*)(A + (size_t)rA[i] * 128 + k0n + kqA[i]);
            pb[0] = *(const float4*)(W + (size_t)(k0n + kB) * Nout + col0 + nB);
            pb[1] = *(const float4*)(W + (size_t)(k0n + kB) * Nout + col0 + nB + 4);
        }
        #pragma unroll
        for (int k = 0; k < 16; k++) {
            float4 a0 = *(const float4*)&As[k][ty * 8];
            float4 a1 = *(const float4*)&As[k][ty * 8 + 4];
            const ull* bp = (const ull*)&Bs[k][tx * 8];
            ull b0 = bp[0], b1 = bp[1], b2 = bp[2], b3 = bp[3];
            ull ad[8];
            ad[0] = pack2(a0.x, a0.x); ad[1] = pack2(a0.y, a0.y);
            ad[2] = pack2(a0.z, a0.z); ad[3] = pack2(a0.w, a0.w);
            ad[4] = pack2(a1.x, a1.x); ad[5] = pack2(a1.y, a1.y);
            ad[6] = pack2(a1.z, a1.z); ad[7] = pack2(a1.w, a1.w);
            #pragma unroll
            for (int i = 0; i < 8; i++) {
                acc[i * 4 + 0] = fma2(ad[i], b0, acc[i * 4 + 0]);
                acc[i * 4 + 1] = fma2(ad[i], b1, acc[i * 4 + 1]);
                acc[i * 4 + 2] = fma2(ad[i], b2, acc[i * 4 + 2]);
                acc[i * 4 + 3] = fma2(ad[i], b3, acc[i * 4 + 3]);
            }
        }
    }
}

// --- QKV: grid (79, 4, 3). z=0 -> q (f32), z=1 -> k (f16), z=2 -> v (f16)
__global__ __launch_bounds__(256, 2) void qkv_gemm(
    const float* __restrict__ A,
    const float* __restrict__ Wq, const float* __restrict__ bq,
    const float* __restrict__ Wk, const float* __restrict__ bk,
    const float* __restrict__ Wv, const float* __restrict__ bv)
{
    __shared__ float As[16][132];
    __shared__ float Bs[16][132];
    int tid = threadIdx.x;
    int tx = tid & 15;
    int ty = tid >> 4;
    int row0 = blockIdx.x * 128;
    int col0 = blockIdx.y * 128;
    int z = blockIdx.z;
    const float* W = (z == 0) ? Wq : (z == 1) ? Wk : Wv;
    const float* bias = (z == 0) ? bq : (z == 1) ? bk : bv;

    ull acc[32];
    gemm_core(A, W, row0, col0, 512, NTOTc, acc, As, Bs);

    int gc = col0 + tx * 8;
    float bvv[8];
    #pragma unroll
    for (int j = 0; j < 8; j++) bvv[j] = bias[gc + j];

    #pragma unroll
    for (int i = 0; i < 8; i++) {
        int gr = row0 + ty * 8 + i;
        if (gr >= Nn) continue;
        float c[8];
        #pragma unroll
        for (int j = 0; j < 4; j++) {
            float2 p = unpack2(acc[i * 4 + j]);
            c[2 * j]     = p.x + bvv[2 * j];
            c[2 * j + 1] = p.y + bvv[2 * j + 1];
        }
        size_t o = (size_t)gr * 512 + gc;
        if (z == 0) {
            *(float4*)(g_q + o)     = make_float4(c[0], c[1], c[2], c[3]);
            *(float4*)(g_q + o + 4) = make_float4(c[4], c[5], c[6], c[7]);
        } else {
            __half2 h0 = __floats2half2_rn(c[0], c[1]);
            __half2 h1 = __floats2half2_rn(c[2], c[3]);
            __half2 h2 = __floats2half2_rn(c[4], c[5]);
            __half2 h3 = __floats2half2_rn(c[6], c[7]);
            uint4 pk = make_uint4(*(unsigned*)&h0, *(unsigned*)&h1,
                                  *(unsigned*)&h2, *(unsigned*)&h3);
            if (z == 1) *(uint4*)(g_kh + o) = pk;
            else        *(uint4*)(g_vh + o) = pk;
        }
    }
}

// --- skip for rows < 10000 only: grid 79. Raw output (attention adds BN later).
__global__ __launch_bounds__(256, 2) void skip_gemm(
    const float* __restrict__ A, const float* __restrict__ W,
    const float* __restrict__ bias, float* __restrict__ C)
{
    __shared__ float As[16][132];
    __shared__ float Bs[16][132];
    int tid = threadIdx.x;
    int tx = tid & 15;
    int ty = tid >> 4;
    int row0 = blockIdx.x * 128;

    ull acc[32];
    gemm_core(A, W, row0, 0, 128, NTOTc, acc, As, Bs);

    int gc = tx * 8;
    float bvv[8];
    #pragma unroll
    for (int j = 0; j < 8; j++) bvv[j] = bias[gc + j];

    #pragma unroll
    for (int i = 0; i < 8; i++) {
        int gr = row0 + ty * 8 + i;
        if (gr >= Nn) continue;
        float c[8];
        #pragma unroll
        for (int j = 0; j < 4; j++) {
            float2 p = unpack2(acc[i * 4 + j]);
            c[2 * j]     = p.x + bvv[2 * j];
            c[2 * j + 1] = p.y + bvv[2 * j + 1];
        }
        float* dstp = C + (size_t)gr * 128 + gc;
        *(float4*)(dstp)     = make_float4(c[0], c[1], c[2], c[3]);
        *(float4*)(dstp + 4) = make_float4(c[4], c[5], c[6], c[7]);
    }
}

// ================= hybrid: static-path GEMM (blocks < SBLK) + attention =================
__global__ __launch_bounds__(256, 2) void hybrid_kernel(
    const float* __restrict__ hcur, const float* __restrict__ Wsk,
    const float* __restrict__ bsk,
    const float* __restrict__ q, const __half* __restrict__ kh,
    const __half* __restrict__ vh, float* __restrict__ hnext,
    const float* __restrict__ bng, const float* __restrict__ bnb,
    const float* __restrict__ bnm, const float* __restrict__ bnv)
{
    __shared__ __align__(16) float smbuf[16 * 132 * 2];
    int tid = threadIdx.x;

    if (blockIdx.x < SBLK) {
        // ---- static path: rows 10000 + bid*128, full BN+ReLU epilogue ----
        float (*As)[132] = (float(*)[132])smbuf;
        float (*Bs)[132] = (float(*)[132])(smbuf + 16 * 132);
        int tx = tid & 15;
        int ty = tid >> 4;
        int row0 = Nn + blockIdx.x * 128;

        ull acc[32];
        gemm_core(hcur, Wsk, row0, 0, 128, NTOTc, acc, As, Bs);

        int gc = tx * 8;
        float bvv[8], scv[8], mnv[8], btv[8];
        #pragma unroll
        for (int j = 0; j < 8; j++) {
            bvv[j] = bsk[gc + j];
            scv[j] = bng[gc + j] * rsqrtf(bnv[gc + j] + 1e-5f);
            mnv[j] = bnm[gc + j];
            btv[j] = bnb[gc + j];
        }

        #pragma unroll
        for (int i = 0; i < 8; i++) {
            int gr = row0 + ty * 8 + i;
            if (gr >= NTOTc) continue;
            float c[8];
            #pragma unroll
            for (int j = 0; j < 4; j++) {
                float2 p = unpack2(acc[i * 4 + j]);
                c[2 * j]     = p.x + bvv[2 * j];
                c[2 * j + 1] = p.y + bvv[2 * j + 1];
            }
            #pragma unroll
            for (int j = 0; j < 8; j++)
                c[j] = fmaxf((c[j] - mnv[j]) * scv[j] + btv[j], 0.f);
            float* dstp = hnext + (size_t)gr * 128 + gc;
            *(float4*)(dstp)     = make_float4(c[0], c[1], c[2], c[3]);
            *(float4*)(dstp + 4) = make_float4(c[4], c[5], c[6], c[7]);
        }
        return;
    }

    // ---- attention: 2 nodes per block, warp -> (node, head) ----
    float (*outsh)[128] = (float(*)[128])smbuf;   // [8][128]
    int warp = tid >> 5;
    int lane = tid & 31;
    int n = (blockIdx.x - SBLK) * 2 + (warp >> 2);
    int head = warp & 3;

    const float4 qr = *(const float4*)(q + (size_t)n * 512 + head * 128 + lane * 4);
    int b = g_off[n], e = g_off[n + 1];

    float m1 = -1e30f, d1 = 0.f, x10 = 0.f, x11 = 0.f, x12 = 0.f, x13 = 0.f;
    float m2 = -1e30f, d2 = 0.f, x20 = 0.f, x21 = 0.f, x22 = 0.f, x23 = 0.f;

    int ei = b;
    for (; ei + 1 < e; ei += 2) {
        int s1 = g_srcs[ei];
        int s2 = g_srcs[ei + 1];
        size_t base1 = (size_t)s1 * 512 + head * 128;
        size_t base2 = (size_t)s2 * 512 + head * 128;
        uint2 kr1 = ((const uint2*)(kh + base1))[lane];
        uint2 kr2 = ((const uint2*)(kh + base2))[lane];
        float2 ka1 = __half22float2(*(const __half2*)&kr1.x);
        float2 kb1 = __half22float2(*(const __half2*)&kr1.y);
        float2 ka2 = __half22float2(*(const __half2*)&kr2.x);
        float2 kb2 = __half22float2(*(const __half2*)&kr2.y);
        float p1 = qr.x * ka1.x + qr.y * ka1.y + qr.z * kb1.x + qr.w * kb1.y;
        float p2 = qr.x * ka2.x + qr.y * ka2.y + qr.z * kb2.x + qr.w * kb2.y;
        #pragma unroll
        for (int o = 16; o; o >>= 1) {
            p1 += __shfl_xor_sync(0xffffffffu, p1, o);
            p2 += __shfl_xor_sync(0xffffffffu, p2, o);
        }
        uint2 vr1 = ((const uint2*)(vh + base1))[lane];
        uint2 vr2 = ((const uint2*)(vh + base2))[lane];
        float a1 = p1 * 0.08838834764831843f;
        float a2 = p2 * 0.08838834764831843f;
        {
            float mn = fmaxf(m1, a1);
            float sc = __expf(m1 - mn);
            float w  = __expf(a1 - mn);
            float2 va = __half22float2(*(const __half2*)&vr1.x);
            float2 vb = __half22float2(*(const __half2*)&vr1.y);
            d1  = d1 * sc + w;
            x10 = x10 * sc + w * va.x;
            x11 = x11 * sc + w * va.y;
            x12 = x12 * sc + w * vb.x;
            x13 = x13 * sc + w * vb.y;
            m1 = mn;
        }
        {
            float mn = fmaxf(m2, a2);
            float sc = __expf(m2 - mn);
            float w  = __expf(a2 - mn);
            float2 va = __half22float2(*(const __half2*)&vr2.x);
            float2 vb = __half22float2(*(const __half2*)&vr2.y);
            d2  = d2 * sc + w;
            x20 = x20 * sc + w * va.x;
            x21 = x21 * sc + w * va.y;
            x22 = x22 * sc + w * vb.x;
            x23 = x23 * sc + w * vb.y;
            m2 = mn;
        }
    }
    if (ei < e) {
        int s = g_srcs[ei];
        size_t base = (size_t)s * 512 + head * 128;
        uint2 kr = ((const uint2*)(kh + base))[lane];
        float2 ka = __half22float2(*(const __half2*)&kr.x);
        float2 kb = __half22float2(*(const __half2*)&kr.y);
        float p = qr.x * ka.x + qr.y * ka.y + qr.z * kb.x + qr.w * kb.y;
        #pragma unroll
        for (int o = 16; o; o >>= 1) p += __shfl_xor_sync(0xffffffffu, p, o);
        float a = p * 0.08838834764831843f;
        float mn = fmaxf(m1, a);
        float sc = __expf(m1 - mn);
        float w  = __expf(a - mn);
        uint2 vr = ((const uint2*)(vh + base))[lane];
        float2 va = __half22float2(*(const __half2*)&vr.x);
        float2 vb = __half22float2(*(const __half2*)&vr.y);
        d1  = d1 * sc + w;
        x10 = x10 * sc + w * va.x;
        x11 = x11 * sc + w * va.y;
        x12 = x12 * sc + w * vb.x;
        x13 = x13 * sc + w * vb.y;
        m1 = mn;
    }
    {
        float mn = fmaxf(m1, m2);
        float s1 = __expf(m1 - mn);
        float s2 = (d2 > 0.f) ? __expf(m2 - mn) : 0.f;
        d1  = d1 * s1 + d2 * s2;
        x10 = x10 * s1 + x20 * s2;
        x11 = x11 * s1 + x21 * s2;
        x12 = x12 * s1 + x22 * s2;
        x13 = x13 * s1 + x23 * s2;
    }
    float inv = 1.f / (d1 + 1e-16f);
    outsh[warp][lane * 4 + 0] = x10 * inv;
    outsh[warp][lane * 4 + 1] = x11 * inv;
    outsh[warp][lane * 4 + 2] = x12 * inv;
    outsh[warp][lane * 4 + 3] = x13 * inv;
    __syncthreads();

    int half = tid >> 7;            // 0/1 -> node
    int ch = tid & 127;             // channel
    int node = (blockIdx.x - SBLK) * 2 + half;
    float val = hnext[(size_t)node * 128 + ch] +
                0.25f * (outsh[half * 4 + 0][ch] + outsh[half * 4 + 1][ch] +
                         outsh[half * 4 + 2][ch] + outsh[half * 4 + 3][ch]);
    float sc = bng[ch] * rsqrtf(bnv[ch] + 1e-5f);
    float r = (val - bnm[ch]) * sc + bnb[ch];
    hnext[(size_t)node * 128 + ch] = fmaxf(r, 0.f);
}

// ================= two-stage sort-pool =================
__global__ __launch_bounds__(256) void sp1_kernel(const float* __restrict__ h)
{
    int g = blockIdx.x / 10;
    int part = blockIdx.x % 10;
    int t = threadIdx.x;
    __shared__ unsigned int skey[1000];
    __shared__ ull sbest[256];

    for (int i = t; i < 1000; i += 256) {
        float val = h[((size_t)g * Nn + part * 1000 + i) * 128 + 127];
        unsigned int bits = __float_as_uint(val);
        skey[i] = (bits & 0x80000000u) ? ~bits : (bits | 0x80000000u);
    }
    __syncthreads();

    for (int kk = 0; kk < Kk; kk++) {
        ull best = 0ull;
        for (int i = t; i < 1000; i += 256) {
            ull key = ((ull)skey[i] << 32) |
                      (unsigned int)(0xFFFFFFFFu - (part * 1000 + i));
            if (key > best) best = key;
        }
        sbest[t] = best;
        __syncthreads();
        for (int s = 128; s > 0; s >>= 1) {
            if (t < s) { ull o = sbest[t + s]; if (o > sbest[t]) sbest[t] = o; }
            __syncthreads();
        }
        if (t == 0) {
            ull top = sbest[0];
            int nig = (int)(0xFFFFFFFFu - (unsigned int)(top & 0xFFFFFFFFull));
            g_cand[blockIdx.x * Kk + kk] = top;
            skey[nig - part * 1000] = 0;
        }
        __syncthreads();
    }
}

__global__ __launch_bounds__(256) void sp2_kernel(const float* __restrict__ h,
                                                  const float* __restrict__ age)
{
    int g = blockIdx.x;
    int t = threadIdx.x;
    __shared__ ull cand[300];
    __shared__ ull sbest[256];

    for (int i = t; i < 300; i += 256) cand[i] = g_cand[g * 300 + i];
    __syncthreads();

    for (int kk = 0; kk < Kk; kk++) {
        ull best = 0ull;
        for (int i = t; i < 300; i += 256) { ull k = cand[i]; if (k > best) best = k; }
        sbest[t] = best;
        __syncthreads();
        for (int s = 128; s > 0; s >>= 1) {
            if (t < s) { ull o = sbest[t + s]; if (o > sbest[t]) sbest[t] = o; }
            __syncthreads();
        }
        ull top = sbest[0];
        if (t == 0) {
            int nig = (int)(0xFFFFFFFFu - (unsigned int)(top & 0xFFFFFFFFull));
            g_topk[g * Kk + kk] = nig;
        }
        __syncthreads();
        for (int i = t; i < 300; i += 256) if (cand[i] == top) cand[i] = 0;
        __syncthreads();
    }

    for (int i = t; i < Kk * 128; i += 256) {
        int kkk = i >> 7, c = i & 127;
        int n = g_topk[g * Kk + kkk];
        g_z[g * ZLEN + i] = h[((size_t)g * Nn + n) * 128 + c];
    }
    if (t == 0) g_z[g * ZLEN + Kk * 128] = age[g];
}

// ================= MLP head =================
__global__ __launch_bounds__(512) void mlp_kernel(
    const float* __restrict__ W1, const float* __restrict__ b1,
    const float* __restrict__ W2, const float* __restrict__ b2,
    float* __restrict__ out)
{
    int g = blockIdx.x;
    int t = threadIdx.x;
    __shared__ float zs[ZLEN];
    __shared__ float red0[512];
    __shared__ float red1[512];

    for (int i = t; i < ZLEN; i += 512) zs[i] = g_z[g * ZLEN + i];
    __syncthreads();

    float acc = b1[t];
    for (int j = 0; j < ZLEN; j++) acc += zs[j] * W1[(size_t)j * 512 + t];
    float hid = fmaxf(acc, 0.f);

    red0[t] = hid * W2[t * 2 + 0];
    red1[t] = hid * W2[t * 2 + 1];
    __syncthreads();
    for (int s = 256; s > 0; s >>= 1) {
        if (t < s) { red0[t] += red0[t + s]; red1[t] += red1[t + s]; }
        __syncthreads();
    }
    if (t == 0) {
        float o0 = red0[0] + b2[0];
        float o1 = red1[0] + b2[1];
        float mx = fmaxf(o0, o1);
        float lse = mx + logf(expf(o0 - mx) + expf(o1 - mx));
        out[g * 2 + 0] = o0 - lse;
        out[g * 2 + 1] = o1 - lse;
    }
}

// ================= launch =================
extern "C" void kernel_launch(void* const* d_in, const int* in_sizes, int n_in,
                              void* d_out, int out_size)
{
    const float* x     = (const float*)d_in[0];
    const int*   eidx  = (const int*)  d_in[1];
    const float* age   = (const float*)d_in[2];
    const float* Wq    = (const float*)d_in[3];
    const float* bq    = (const float*)d_in[4];
    const float* Wk    = (const float*)d_in[5];
    const float* bk    = (const float*)d_in[6];
    const float* Wv    = (const float*)d_in[7];
    const float* bv    = (const float*)d_in[8];
    const float* Wsk   = (const float*)d_in[9];
    const float* bsk   = (const float*)d_in[10];
    const float* bn_g  = (const float*)d_in[11];
    const float* bn_b  = (const float*)d_in[12];
    const float* bn_m  = (const float*)d_in[13];
    const float* bn_v  = (const float*)d_in[14];
    const float* W1    = (const float*)d_in[15];
    const float* b1    = (const float*)d_in[16];
    const float* W2    = (const float*)d_in[17];
    const float* b2    = (const float*)d_in[18];
    float* out = (float*)d_out;

    int E = in_sizes[1] / 2;
    const int* src = eidx;
    const int* dst = eidx + E;

    float *q, *hA, *hB;
    __half *kh, *vh;
    cudaGetSymbolAddress((void**)&q,  g_q);
    cudaGetSymbolAddress((void**)&kh, g_kh);
    cudaGetSymbolAddress((void**)&vh, g_vh);
    cudaGetSymbolAddress((void**)&hA, g_hA);
    cudaGetSymbolAddress((void**)&hB, g_hB);

    // CSR build
    zero_deg_kernel<<<(Nn + 256) / 256, 256>>>();
    hist_kernel<<<(E + 255) / 256, 256>>>(dst, E);
    scan_kernel<<<1, 1024>>>();
    scatter_kernel<<<(E + 255) / 256, 256>>>(src, dst, E);

    const float* hcur = x;
    float* hnext = hA;
    for (int l = 0; l < 3; l++) {
        dim3 gq((Nn + 127) / 128, 4, 3);
        qkv_gemm<<<gq, 256>>>(hcur, Wq, bq, Wk, bk, Wv, bv);
        skip_gemm<<<(Nn + 127) / 128, 256>>>(hcur, Wsk, bsk, hnext);
        hybrid_kernel<<<SBLK + Nn / 2, 256>>>(hcur, Wsk, bsk, q, kh, vh, hnext,
                                              bn_g + l * 128, bn_b + l * 128,
                                              bn_m + l * 128, bn_v + l * 128);
        hcur = hnext;
        hnext = (hcur == hA) ? hB : hA;
    }

    sp1_kernel<<<80, 256>>>(hcur);
    sp2_kernel<<<Bg, 256>>>(hcur, age);
    mlp_kernel<<<Bg, 512>>>(W1, b1, W2, b2, out);
}

// round 14
// speedup vs baseline: 1.3210x; 1.3210x over previous
#include <cuda_runtime.h>
#include <cuda_fp16.h>
#include <cstdint>
#include <math.h>

typedef unsigned long long ull;

// ---- static problem config ----
#define Nn    10000
#define NTOTc 80000
#define Bg    8
#define Emax  320000
#define Kk    30
#define ZLEN  3841           // K*C + 1

// fused GEMM launch: 948 qkv tiles (3 x 316) + 625 skip tiles
#define QKVB  948
#define GEMMB 1573

// ---- scratch ----
__device__ float  g_q[Nn * 512];
__device__ __half g_kh[Nn * 512];
__device__ __half g_vh[Nn * 512];
__device__ float  g_hA[(size_t)NTOTc * 128];
__device__ float  g_hB[(size_t)NTOTc * 128];
__device__ int    g_deg[Nn + 1];
__device__ int    g_off[Nn + 1];
__device__ int    g_cur[Nn];
__device__ int    g_srcs[Emax];
__device__ ull    g_cand[80 * Kk];
__device__ float  g_z[Bg * ZLEN];
__device__ int    g_topk[Bg * Kk];

// ---- packed f32x2 helpers ----
static __device__ __forceinline__ ull pack2(float lo, float hi) {
    ull d; asm("mov.b64 %0, {%1, %2};" : "=l"(d) : "f"(lo), "f"(hi)); return d;
}
static __device__ __forceinline__ ull fma2(ull a, ull b, ull c) {
    ull d; asm("fma.rn.f32x2 %0, %1, %2, %3;" : "=l"(d) : "l"(a), "l"(b), "l"(c)); return d;
}
static __device__ __forceinline__ float2 unpack2(ull d) {
    float2 f; asm("mov.b64 {%0, %1}, %2;" : "=f"(f.x), "=f"(f.y) : "l"(d)); return f;
}

// ================= CSR build =================
__global__ void zero_deg_kernel() {
    int i = blockIdx.x * blockDim.x + threadIdx.x;
    if (i <= Nn) g_deg[i] = 0;
}
__global__ void hist_kernel(const int* __restrict__ dst, int E) {
    int e = blockIdx.x * blockDim.x + threadIdx.x;
    if (e < E) atomicAdd(&g_deg[dst[e]], 1);
}
__global__ __launch_bounds__(1024) void scan_kernel() {
    __shared__ int partial[1024];
    const int PER = 10;
    int t = threadIdx.x;
    int base = t * PER;
    int local[PER];
    int s = 0;
    #pragma unroll
    for (int i = 0; i < PER; i++) {
        int idx = base + i;
        int dv = (idx < Nn) ? g_deg[idx] : 0;
        local[i] = s; s += dv;
    }
    partial[t] = s;
    __syncthreads();
    for (int offd = 1; offd < 1024; offd <<= 1) {
        int addv = 0;
        if (t >= offd) addv = partial[t - offd];
        __syncthreads();
        if (t >= offd) partial[t] += addv;
        __syncthreads();
    }
    int pre = (t > 0) ? partial[t - 1] : 0;
    #pragma unroll
    for (int i = 0; i < PER; i++) {
        int idx = base + i;
        if (idx < Nn) { int o = pre + local[i]; g_off[idx] = o; g_cur[idx] = o; }
    }
    if (t == 1023) g_off[Nn] = partial[1023];
}
__global__ void scatter_kernel(const int* __restrict__ src,
                               const int* __restrict__ dst, int E) {
    int e = blockIdx.x * blockDim.x + threadIdx.x;
    if (e < E) {
        int d = dst[e];
        int p = atomicAdd(&g_cur[d], 1);
        g_srcs[p] = src[e];
    }
}

// ================= f32x2 GEMM core, double-buffered (1 sync/chunk) =================
// As[buf][k][r] transposed A, Bs[buf][k][n] natural W.
// acc[i*4+j] = (C[ty*8+i][tx*8+2j], C[ty*8+i][tx*8+2j+1])
static __device__ __forceinline__ void gemm_core(
    const float* __restrict__ A, const float* __restrict__ W,
    int row0, int col0, int Nout, ull* acc,
    float (*As)[16][132], float (*Bs)[16][132])
{
    int tid = threadIdx.x;
    int tx = tid & 15;
    int ty = tid >> 4;

    #pragma unroll
    for (int i = 0; i < 32; i++) acc[i] = 0ull;

    int rA[2], kqA[2], sr[2];
    float4 pa[2], pb[2];
    #pragma unroll
    for (int i = 0; i < 2; i++) {
        int f = tid + i * 256;
        int rr = row0 + (f >> 2);
        rA[i] = (rr < NTOTc) ? rr : (NTOTc - 1);   // clamp; stores guarded in epilogue
        sr[i] = f >> 2;
        kqA[i] = (f & 3) * 4;
        pa[i] = *(const float4*)(A + (size_t)rA[i] * 128 + kqA[i]);
    }
    int kB = tid >> 4;
    int nB = (tid & 15) * 8;
    pb[0] = *(const float4*)(W + (size_t)kB * Nout + col0 + nB);
    pb[1] = *(const float4*)(W + (size_t)kB * Nout + col0 + nB + 4);

    // stage chunk 0 into buffer 0
    #pragma unroll
    for (int i = 0; i < 2; i++) {
        As[0][kqA[i] + 0][sr[i]] = pa[i].x;
        As[0][kqA[i] + 1][sr[i]] = pa[i].y;
        As[0][kqA[i] + 2][sr[i]] = pa[i].z;
        As[0][kqA[i] + 3][sr[i]] = pa[i].w;
    }
    *(float4*)&Bs[0][kB][nB]     = pb[0];
    *(float4*)&Bs[0][kB][nB + 4] = pb[1];
    __syncthreads();

    #pragma unroll
    for (int kc = 0; kc < 8; kc++) {
        int cur = kc & 1;
        int nxt = cur ^ 1;
        if (kc < 7) {
            int k0n = (kc + 1) * 16;
            #pragma unroll
            for (int i = 0; i < 2; i++)
                pa[i] = *(const float4*)(A + (size_t)rA[i] * 128 + k0n + kqA[i]);
            pb[0] = *(const float4*)(W + (size_t)(k0n + kB) * Nout + col0 + nB);
            pb[1] = *(const float4*)(W + (size_t)(k0n + kB) * Nout + col0 + nB + 4);
        }
        #pragma unroll
        for (int k = 0; k < 16; k++) {
            float4 a0 = *(const float4*)&As[cur][k][ty * 8];
            float4 a1 = *(const float4*)&As[cur][k][ty * 8 + 4];
            const ull* bp = (const ull*)&Bs[cur][k][tx * 8];
            ull b0 = bp[0], b1 = bp[1], b2 = bp[2], b3 = bp[3];
            ull ad[8];
            ad[0] = pack2(a0.x, a0.x); ad[1] = pack2(a0.y, a0.y);
            ad[2] = pack2(a0.z, a0.z); ad[3] = pack2(a0.w, a0.w);
            ad[4] = pack2(a1.x, a1.x); ad[5] = pack2(a1.y, a1.y);
            ad[6] = pack2(a1.z, a1.z); ad[7] = pack2(a1.w, a1.w);
            #pragma unroll
            for (int i = 0; i < 8; i++) {
                acc[i * 4 + 0] = fma2(ad[i], b0, acc[i * 4 + 0]);
                acc[i * 4 + 1] = fma2(ad[i], b1, acc[i * 4 + 1]);
                acc[i * 4 + 2] = fma2(ad[i], b2, acc[i * 4 + 2]);
                acc[i * 4 + 3] = fma2(ad[i], b3, acc[i * 4 + 3]);
            }
        }
        if (kc < 7) {
            #pragma unroll
            for (int i = 0; i < 2; i++) {
                As[nxt][kqA[i] + 0][sr[i]] = pa[i].x;
                As[nxt][kqA[i] + 1][sr[i]] = pa[i].y;
                As[nxt][kqA[i] + 2][sr[i]] = pa[i].z;
                As[nxt][kqA[i] + 3][sr[i]] = pa[i].w;
            }
            *(float4*)&Bs[nxt][kB][nB]     = pb[0];
            *(float4*)&Bs[nxt][kB][nB + 4] = pb[1];
        }
        __syncthreads();
    }
}

// ================= fused GEMM launch: qkv (0..947) | skip (948..1572) =================
__global__ __launch_bounds__(256, 2) void gemm_kernel(
    const float* __restrict__ A,
    const float* __restrict__ Wq, const float* __restrict__ bq,
    const float* __restrict__ Wk, const float* __restrict__ bk,
    const float* __restrict__ Wv, const float* __restrict__ bv,
    const float* __restrict__ Wsk, const float* __restrict__ bsk,
    float* __restrict__ C,
    const float* __restrict__ bng, const float* __restrict__ bnb,
    const float* __restrict__ bnm, const float* __restrict__ bnv)
{
    __shared__ __align__(16) float As[2][16][132];
    __shared__ __align__(16) float Bs[2][16][132];
    int tid = threadIdx.x;
    int tx = tid & 15;
    int ty = tid >> 4;
    int bid = blockIdx.x;

    if (bid < QKVB) {
        int z = bid / 316;
        int b2 = bid - z * 316;
        int row0 = (b2 % 79) * 128;
        int col0 = (b2 / 79) * 128;
        const float* W = (z == 0) ? Wq : (z == 1) ? Wk : Wv;
        const float* bias = (z == 0) ? bq : (z == 1) ? bk : bv;

        ull acc[32];
        gemm_core(A, W, row0, col0, 512, acc, As, Bs);

        int gc = col0 + tx * 8;
        float bvv[8];
        #pragma unroll
        for (int j = 0; j < 8; j++) bvv[j] = bias[gc + j];

        #pragma unroll
        for (int i = 0; i < 8; i++) {
            int gr = row0 + ty * 8 + i;
            if (gr >= Nn) continue;
            float c[8];
            #pragma unroll
            for (int j = 0; j < 4; j++) {
                float2 p = unpack2(acc[i * 4 + j]);
                c[2 * j]     = p.x + bvv[2 * j];
                c[2 * j + 1] = p.y + bvv[2 * j + 1];
            }
            size_t o = (size_t)gr * 512 + gc;
            if (z == 0) {
                *(float4*)(g_q + o)     = make_float4(c[0], c[1], c[2], c[3]);
                *(float4*)(g_q + o + 4) = make_float4(c[4], c[5], c[6], c[7]);
            } else {
                __half2 h0 = __floats2half2_rn(c[0], c[1]);
                __half2 h1 = __floats2half2_rn(c[2], c[3]);
                __half2 h2 = __floats2half2_rn(c[4], c[5]);
                __half2 h3 = __floats2half2_rn(c[6], c[7]);
                uint4 pk = make_uint4(*(unsigned*)&h0, *(unsigned*)&h1,
                                      *(unsigned*)&h2, *(unsigned*)&h3);
                if (z == 1) *(uint4*)(g_kh + o) = pk;
                else        *(uint4*)(g_vh + o) = pk;
            }
        }
    } else {
        // skip GEMM: rows >= Nn get BN+ReLU; rows < Nn raw (attention finishes them)
        int row0 = (bid - QKVB) * 128;

        ull acc[32];
        gemm_core(A, Wsk, row0, 0, 128, acc, As, Bs);

        int gc = tx * 8;
        float bvv[8], scv[8], mnv[8], btv[8];
        #pragma unroll
        for (int j = 0; j < 8; j++) {
            bvv[j] = bsk[gc + j];
            scv[j] = bng[gc + j] * rsqrtf(bnv[gc + j] + 1e-5f);
            mnv[j] = bnm[gc + j];
            btv[j] = bnb[gc + j];
        }

        #pragma unroll
        for (int i = 0; i < 8; i++) {
            int gr = row0 + ty * 8 + i;
            float c[8];
            #pragma unroll
            for (int j = 0; j < 4; j++) {
                float2 p = unpack2(acc[i * 4 + j]);
                c[2 * j]     = p.x + bvv[2 * j];
                c[2 * j + 1] = p.y + bvv[2 * j + 1];
            }
            if (gr >= Nn) {
                #pragma unroll
                for (int j = 0; j < 8; j++)
                    c[j] = fmaxf((c[j] - mnv[j]) * scv[j] + btv[j], 0.f);
            }
            float* dstp = C + (size_t)gr * 128 + gc;
            *(float4*)(dstp)     = make_float4(c[0], c[1], c[2], c[3]);
            *(float4*)(dstp + 4) = make_float4(c[4], c[5], c[6], c[7]);
        }
    }
}

// ================= fused attention (fp16 K/V, 2-way ILP online softmax) =================
__global__ __launch_bounds__(128) void attn_kernel(
    const float* __restrict__ q, const __half* __restrict__ kh,
    const __half* __restrict__ vh, float* __restrict__ hnext,
    const float* __restrict__ bng, const float* __restrict__ bnb,
    const float* __restrict__ bnm, const float* __restrict__ bnv)
{
    int n = blockIdx.x;
    int warp = threadIdx.x >> 5;
    int lane = threadIdx.x & 31;
    __shared__ float outsh[4][128];

    const float4 qr = *(const float4*)(q + (size_t)n * 512 + warp * 128 + lane * 4);
    int b = g_off[n], e = g_off[n + 1];

    float m1 = -1e30f, d1 = 0.f, x10 = 0.f, x11 = 0.f, x12 = 0.f, x13 = 0.f;
    float m2 = -1e30f, d2 = 0.f, x20 = 0.f, x21 = 0.f, x22 = 0.f, x23 = 0.f;

    int ei = b;
    for (; ei + 1 < e; ei += 2) {
        int s1 = g_srcs[ei];
        int s2 = g_srcs[ei + 1];
        size_t base1 = (size_t)s1 * 512 + warp * 128;
        size_t base2 = (size_t)s2 * 512 + warp * 128;
        uint2 kr1 = ((const uint2*)(kh + base1))[lane];
        uint2 kr2 = ((const uint2*)(kh + base2))[lane];
        float2 ka1 = __half22float2(*(const __half2*)&kr1.x);
        float2 kb1 = __half22float2(*(const __half2*)&kr1.y);
        float2 ka2 = __half22float2(*(const __half2*)&kr2.x);
        float2 kb2 = __half22float2(*(const __half2*)&kr2.y);
        float p1 = qr.x * ka1.x + qr.y * ka1.y + qr.z * kb1.x + qr.w * kb1.y;
        float p2 = qr.x * ka2.x + qr.y * ka2.y + qr.z * kb2.x + qr.w * kb2.y;
        #pragma unroll
        for (int o = 16; o; o >>= 1) {
            p1 += __shfl_xor_sync(0xffffffffu, p1, o);
            p2 += __shfl_xor_sync(0xffffffffu, p2, o);
        }
        uint2 vr1 = ((const uint2*)(vh + base1))[lane];
        uint2 vr2 = ((const uint2*)(vh + base2))[lane];
        float a1 = p1 * 0.08838834764831843f;
        float a2 = p2 * 0.08838834764831843f;
        {
            float mn = fmaxf(m1, a1);
            float sc = __expf(m1 - mn);
            float w  = __expf(a1 - mn);
            float2 va = __half22float2(*(const __half2*)&vr1.x);
            float2 vb = __half22float2(*(const __half2*)&vr1.y);
            d1  = d1 * sc + w;
            x10 = x10 * sc + w * va.x;
            x11 = x11 * sc + w * va.y;
            x12 = x12 * sc + w * vb.x;
            x13 = x13 * sc + w * vb.y;
            m1 = mn;
        }
        {
            float mn = fmaxf(m2, a2);
            float sc = __expf(m2 - mn);
            float w  = __expf(a2 - mn);
            float2 va = __half22float2(*(const __half2*)&vr2.x);
            float2 vb = __half22float2(*(const __half2*)&vr2.y);
            d2  = d2 * sc + w;
            x20 = x20 * sc + w * va.x;
            x21 = x21 * sc + w * va.y;
            x22 = x22 * sc + w * vb.x;
            x23 = x23 * sc + w * vb.y;
            m2 = mn;
        }
    }
    if (ei < e) {
        int s = g_srcs[ei];
        size_t base = (size_t)s * 512 + warp * 128;
        uint2 kr = ((const uint2*)(kh + base))[lane];
        float2 ka = __half22float2(*(const __half2*)&kr.x);
        float2 kb = __half22float2(*(const __half2*)&kr.y);
        float p = qr.x * ka.x + qr.y * ka.y + qr.z * kb.x + qr.w * kb.y;
        #pragma unroll
        for (int o = 16; o; o >>= 1) p += __shfl_xor_sync(0xffffffffu, p, o);
        float a = p * 0.08838834764831843f;
        float mn = fmaxf(m1, a);
        float sc = __expf(m1 - mn);
        float w  = __expf(a - mn);
        uint2 vr = ((const uint2*)(vh + base))[lane];
        float2 va = __half22float2(*(const __half2*)&vr.x);
        float2 vb = __half22float2(*(const __half2*)&vr.y);
        d1  = d1 * sc + w;
        x10 = x10 * sc + w * va.x;
        x11 = x11 * sc + w * va.y;
        x12 = x12 * sc + w * vb.x;
        x13 = x13 * sc + w * vb.y;
        m1 = mn;
    }
    {
        float mn = fmaxf(m1, m2);
        float s1 = __expf(m1 - mn);
        float s2 = (d2 > 0.f) ? __expf(m2 - mn) : 0.f;
        d1  = d1 * s1 + d2 * s2;
        x10 = x10 * s1 + x20 * s2;
        x11 = x11 * s1 + x21 * s2;
        x12 = x12 * s1 + x22 * s2;
        x13 = x13 * s1 + x23 * s2;
    }
    float inv = 1.f / (d1 + 1e-16f);
    outsh[warp][lane * 4 + 0] = x10 * inv;
    outsh[warp][lane * 4 + 1] = x11 * inv;
    outsh[warp][lane * 4 + 2] = x12 * inv;
    outsh[warp][lane * 4 + 3] = x13 * inv;
    __syncthreads();

    int t = threadIdx.x;
    float val = hnext[(size_t)n * 128 + t] +
                0.25f * (outsh[0][t] + outsh[1][t] + outsh[2][t] + outsh[3][t]);
    float sc = bng[t] * rsqrtf(bnv[t] + 1e-5f);
    float r = (val - bnm[t]) * sc + bnb[t];
    hnext[(size_t)n * 128 + t] = fmaxf(r, 0.f);
}

// ================= two-stage sort-pool =================
__global__ __launch_bounds__(256) void sp1_kernel(const float* __restrict__ h)
{
    int g = blockIdx.x / 10;
    int part = blockIdx.x % 10;
    int t = threadIdx.x;
    __shared__ unsigned int skey[1000];
    __shared__ ull sbest[256];

    for (int i = t; i < 1000; i += 256) {
        float val = h[((size_t)g * Nn + part * 1000 + i) * 128 + 127];
        unsigned int bits = __float_as_uint(val);
        skey[i] = (bits & 0x80000000u) ? ~bits : (bits | 0x80000000u);
    }
    __syncthreads();

    for (int kk = 0; kk < Kk; kk++) {
        ull best = 0ull;
        for (int i = t; i < 1000; i += 256) {
            ull key = ((ull)skey[i] << 32) |
                      (unsigned int)(0xFFFFFFFFu - (part * 1000 + i));
            if (key > best) best = key;
        }
        sbest[t] = best;
        __syncthreads();
        for (int s = 128; s > 0; s >>= 1) {
            if (t < s) { ull o = sbest[t + s]; if (o > sbest[t]) sbest[t] = o; }
            __syncthreads();
        }
        if (t == 0) {
            ull top = sbest[0];
            int nig = (int)(0xFFFFFFFFu - (unsigned int)(top & 0xFFFFFFFFull));
            g_cand[blockIdx.x * Kk + kk] = top;
            skey[nig - part * 1000] = 0;
        }
        __syncthreads();
    }
}

__global__ __launch_bounds__(256) void sp2_kernel(const float* __restrict__ h,
                                                  const float* __restrict__ age)
{
    int g = blockIdx.x;
    int t = threadIdx.x;
    __shared__ ull cand[300];
    __shared__ ull sbest[256];

    for (int i = t; i < 300; i += 256) cand[i] = g_cand[g * 300 + i];
    __syncthreads();

    for (int kk = 0; kk < Kk; kk++) {
        ull best = 0ull;
        for (int i = t; i < 300; i += 256) { ull k = cand[i]; if (k > best) best = k; }
        sbest[t] = best;
        __syncthreads();
        for (int s = 128; s > 0; s >>= 1) {
            if (t < s) { ull o = sbest[t + s]; if (o > sbest[t]) sbest[t] = o; }
            __syncthreads();
        }
        ull top = sbest[0];
        if (t == 0) {
            int nig = (int)(0xFFFFFFFFu - (unsigned int)(top & 0xFFFFFFFFull));
            g_topk[g * Kk + kk] = nig;
        }
        __syncthreads();
        for (int i = t; i < 300; i += 256) if (cand[i] == top) cand[i] = 0;
        __syncthreads();
    }

    for (int i = t; i < Kk * 128; i += 256) {
        int kkk = i >> 7, c = i & 127;
        int n = g_topk[g * Kk + kkk];
        g_z[g * ZLEN + i] = h[((size_t)g * Nn + n) * 128 + c];
    }
    if (t == 0) g_z[g * ZLEN + Kk * 128] = age[g];
}

// ================= MLP head =================
__global__ __launch_bounds__(512) void mlp_kernel(
    const float* __restrict__ W1, const float* __restrict__ b1,
    const float* __restrict__ W2, const float* __restrict__ b2,
    float* __restrict__ out)
{
    int g = blockIdx.x;
    int t = threadIdx.x;
    __shared__ float zs[ZLEN];
    __shared__ float red0[512];
    __shared__ float red1[512];

    for (int i = t; i < ZLEN; i += 512) zs[i] = g_z[g * ZLEN + i];
    __syncthreads();

    float acc = b1[t];
    for (int j = 0; j < ZLEN; j++) acc += zs[j] * W1[(size_t)j * 512 + t];
    float hid = fmaxf(acc, 0.f);

    red0[t] = hid * W2[t * 2 + 0];
    red1[t] = hid * W2[t * 2 + 1];
    __syncthreads();
    for (int s = 256; s > 0; s >>= 1) {
        if (t < s) { red0[t] += red0[t + s]; red1[t] += red1[t + s]; }
        __syncthreads();
    }
    if (t == 0) {
        float o0 = red0[0] + b2[0];
        float o1 = red1[0] + b2[1];
        float mx = fmaxf(o0, o1);
        float lse = mx + logf(expf(o0 - mx) + expf(o1 - mx));
        out[g * 2 + 0] = o0 - lse;
        out[g * 2 + 1] = o1 - lse;
    }
}

// ================= launch =================
extern "C" void kernel_launch(void* const* d_in, const int* in_sizes, int n_in,
                              void* d_out, int out_size)
{
    const float* x     = (const float*)d_in[0];
    const int*   eidx  = (const int*)  d_in[1];
    const float* age   = (const float*)d_in[2];
    const float* Wq    = (const float*)d_in[3];
    const float* bq    = (const float*)d_in[4];
    const float* Wk    = (const float*)d_in[5];
    const float* bk    = (const float*)d_in[6];
    const float* Wv    = (const float*)d_in[7];
    const float* bv    = (const float*)d_in[8];
    const float* Wsk   = (const float*)d_in[9];
    const float* bsk   = (const float*)d_in[10];
    const float* bn_g  = (const float*)d_in[11];
    const float* bn_b  = (const float*)d_in[12];
    const float* bn_m  = (const float*)d_in[13];
    const float* bn_v  = (const float*)d_in[14];
    const float* W1    = (const float*)d_in[15];
    const float* b1    = (const float*)d_in[16];
    const float* W2    = (const float*)d_in[17];
    const float* b2    = (const float*)d_in[18];
    float* out = (float*)d_out;

    int E = in_sizes[1] / 2;
    const int* src = eidx;
    const int* dst = eidx + E;

    float *q, *hA, *hB;
    __half *kh, *vh;
    cudaGetSymbolAddress((void**)&q,  g_q);
    cudaGetSymbolAddress((void**)&kh, g_kh);
    cudaGetSymbolAddress((void**)&vh, g_vh);
    cudaGetSymbolAddress((void**)&hA, g_hA);
    cudaGetSymbolAddress((void**)&hB, g_hB);

    // CSR build
    zero_deg_kernel<<<(Nn + 256) / 256, 256>>>();
    hist_kernel<<<(E + 255) / 256, 256>>>(dst, E);
    scan_kernel<<<1, 1024>>>();
    scatter_kernel<<<(E + 255) / 256, 256>>>(src, dst, E);

    const float* hcur = x;
    float* hnext = hA;
    for (int l = 0; l < 3; l++) {
        gemm_kernel<<<GEMMB, 256>>>(hcur, Wq, bq, Wk, bk, Wv, bv, Wsk, bsk, hnext,
                                    bn_g + l * 128, bn_b + l * 128,
                                    bn_m + l * 128, bn_v + l * 128);
        attn_kernel<<<Nn, 128>>>(q, kh, vh, hnext,
                                 bn_g + l * 128, bn_b + l * 128,
                                 bn_m + l * 128, bn_v + l * 128);
        hcur = hnext;
        hnext = (hcur == hA) ? hB : hA;
    }

    sp1_kernel<<<80, 256>>>(hcur);
    sp2_kernel<<<Bg, 256>>>(hcur, age);
    mlp_kernel<<<Bg, 512>>>(W1, b1, W2, b2, out);
}

// round 15
// speedup vs baseline: 1.4305x; 1.0829x over previous
#include <cuda_runtime.h>
#include <cuda_fp16.h>
#include <cstdint>
#include <math.h>

typedef unsigned long long ull;

// ---- static problem config ----
#define Nn    10000
#define NTOTc 80000
#define Bg    8
#define Emax  320000
#define Kk    30
#define ZLEN  3841           // K*C + 1

// fused GEMM launch: 948 qkv tiles (3 x 316) + 625 skip tiles
#define QKVB  948
#define GEMMB 1573

// ---- scratch ----
__device__ float  g_q[Nn * 512];
__device__ __half g_kh[Nn * 512];
__device__ __half g_vh[Nn * 512];
__device__ float  g_hA[(size_t)NTOTc * 128];
__device__ float  g_hB[(size_t)NTOTc * 128];
__device__ int    g_deg[Nn + 1];
__device__ int    g_off[Nn + 1];
__device__ int    g_cur[Nn];
__device__ int    g_srcs[Emax];
__device__ ull    g_cand[80 * Kk];
__device__ float  g_z[Bg * ZLEN];
__device__ int    g_topk[Bg * Kk];
__device__ float  g_hid[Bg * 512];

// ---- packed f32x2 helpers ----
static __device__ __forceinline__ ull pack2(float lo, float hi) {
    ull d; asm("mov.b64 %0, {%1, %2};" : "=l"(d) : "f"(lo), "f"(hi)); return d;
}
static __device__ __forceinline__ ull fma2(ull a, ull b, ull c) {
    ull d; asm("fma.rn.f32x2 %0, %1, %2, %3;" : "=l"(d) : "l"(a), "l"(b), "l"(c)); return d;
}
static __device__ __forceinline__ float2 unpack2(ull d) {
    float2 f; asm("mov.b64 {%0, %1}, %2;" : "=f"(f.x), "=f"(f.y) : "l"(d)); return f;
}

// ================= CSR build =================
__global__ void zero_deg_kernel() {
    int i = blockIdx.x * blockDim.x + threadIdx.x;
    if (i <= Nn) g_deg[i] = 0;
}
__global__ void hist_kernel(const int* __restrict__ dst, int E) {
    int e = blockIdx.x * blockDim.x + threadIdx.x;
    if (e < E) atomicAdd(&g_deg[dst[e]], 1);
}
__global__ __launch_bounds__(1024) void scan_kernel() {
    __shared__ int partial[1024];
    const int PER = 10;
    int t = threadIdx.x;
    int base = t * PER;
    int local[PER];
    int s = 0;
    #pragma unroll
    for (int i = 0; i < PER; i++) {
        int idx = base + i;
        int dv = (idx < Nn) ? g_deg[idx] : 0;
        local[i] = s; s += dv;
    }
    partial[t] = s;
    __syncthreads();
    for (int offd = 1; offd < 1024; offd <<= 1) {
        int addv = 0;
        if (t >= offd) addv = partial[t - offd];
        __syncthreads();
        if (t >= offd) partial[t] += addv;
        __syncthreads();
    }
    int pre = (t > 0) ? partial[t - 1] : 0;
    #pragma unroll
    for (int i = 0; i < PER; i++) {
        int idx = base + i;
        if (idx < Nn) { int o = pre + local[i]; g_off[idx] = o; g_cur[idx] = o; }
    }
    if (t == 1023) g_off[Nn] = partial[1023];
}
__global__ void scatter_kernel(const int* __restrict__ src,
                               const int* __restrict__ dst, int E) {
    int e = blockIdx.x * blockDim.x + threadIdx.x;
    if (e < E) {
        int d = dst[e];
        int p = atomicAdd(&g_cur[d], 1);
        g_srcs[p] = src[e];
    }
}

// ================= f32x2 GEMM core, double-buffered (1 sync/chunk) =================
static __device__ __forceinline__ void gemm_core(
    const float* __restrict__ A, const float* __restrict__ W,
    int row0, int col0, int Nout, ull* acc,
    float (*As)[16][132], float (*Bs)[16][132])
{
    int tid = threadIdx.x;
    int tx = tid & 15;
    int ty = tid >> 4;

    #pragma unroll
    for (int i = 0; i < 32; i++) acc[i] = 0ull;

    int rA[2], kqA[2], sr[2];
    float4 pa[2], pb[2];
    #pragma unroll
    for (int i = 0; i < 2; i++) {
        int f = tid + i * 256;
        int rr = row0 + (f >> 2);
        rA[i] = (rr < NTOTc) ? rr : (NTOTc - 1);
        sr[i] = f >> 2;
        kqA[i] = (f & 3) * 4;
        pa[i] = *(const float4*)(A + (size_t)rA[i] * 128 + kqA[i]);
    }
    int kB = tid >> 4;
    int nB = (tid & 15) * 8;
    pb[0] = *(const float4*)(W + (size_t)kB * Nout + col0 + nB);
    pb[1] = *(const float4*)(W + (size_t)kB * Nout + col0 + nB + 4);

    #pragma unroll
    for (int i = 0; i < 2; i++) {
        As[0][kqA[i] + 0][sr[i]] = pa[i].x;
        As[0][kqA[i] + 1][sr[i]] = pa[i].y;
        As[0][kqA[i] + 2][sr[i]] = pa[i].z;
        As[0][kqA[i] + 3][sr[i]] = pa[i].w;
    }
    *(float4*)&Bs[0][kB][nB]     = pb[0];
    *(float4*)&Bs[0][kB][nB + 4] = pb[1];
    __syncthreads();

    #pragma unroll
    for (int kc = 0; kc < 8; kc++) {
        int cur = kc & 1;
        int nxt = cur ^ 1;
        if (kc < 7) {
            int k0n = (kc + 1) * 16;
            #pragma unroll
            for (int i = 0; i < 2; i++)
                pa[i] = *(const float4*)(A + (size_t)rA[i] * 128 + k0n + kqA[i]);
            pb[0] = *(const float4*)(W + (size_t)(k0n + kB) * Nout + col0 + nB);
            pb[1] = *(const float4*)(W + (size_t)(k0n + kB) * Nout + col0 + nB + 4);
        }
        #pragma unroll
        for (int k = 0; k < 16; k++) {
            float4 a0 = *(const float4*)&As[cur][k][ty * 8];
            float4 a1 = *(const float4*)&As[cur][k][ty * 8 + 4];
            const ull* bp = (const ull*)&Bs[cur][k][tx * 8];
            ull b0 = bp[0], b1 = bp[1], b2 = bp[2], b3 = bp[3];
            ull ad[8];
            ad[0] = pack2(a0.x, a0.x); ad[1] = pack2(a0.y, a0.y);
            ad[2] = pack2(a0.z, a0.z); ad[3] = pack2(a0.w, a0.w);
            ad[4] = pack2(a1.x, a1.x); ad[5] = pack2(a1.y, a1.y);
            ad[6] = pack2(a1.z, a1.z); ad[7] = pack2(a1.w, a1.w);
            #pragma unroll
            for (int i = 0; i < 8; i++) {
                acc[i * 4 + 0] = fma2(ad[i], b0, acc[i * 4 + 0]);
                acc[i * 4 + 1] = fma2(ad[i], b1, acc[i * 4 + 1]);
                acc[i * 4 + 2] = fma2(ad[i], b2, acc[i * 4 + 2]);
                acc[i * 4 + 3] = fma2(ad[i], b3, acc[i * 4 + 3]);
            }
        }
        if (kc < 7) {
            #pragma unroll
            for (int i = 0; i < 2; i++) {
                As[nxt][kqA[i] + 0][sr[i]] = pa[i].x;
                As[nxt][kqA[i] + 1][sr[i]] = pa[i].y;
                As[nxt][kqA[i] + 2][sr[i]] = pa[i].z;
                As[nxt][kqA[i] + 3][sr[i]] = pa[i].w;
            }
            *(float4*)&Bs[nxt][kB][nB]     = pb[0];
            *(float4*)&Bs[nxt][kB][nB + 4] = pb[1];
        }
        __syncthreads();
    }
}

// ================= fused GEMM launch: qkv (0..947) | skip (948..1572) =================
__global__ __launch_bounds__(256, 2) void gemm_kernel(
    const float* __restrict__ A,
    const float* __restrict__ Wq, const float* __restrict__ bq,
    const float* __restrict__ Wk, const float* __restrict__ bk,
    const float* __restrict__ Wv, const float* __restrict__ bv,
    const float* __restrict__ Wsk, const float* __restrict__ bsk,
    float* __restrict__ C,
    const float* __restrict__ bng, const float* __restrict__ bnb,
    const float* __restrict__ bnm, const float* __restrict__ bnv)
{
    __shared__ __align__(16) float As[2][16][132];
    __shared__ __align__(16) float Bs[2][16][132];
    int tid = threadIdx.x;
    int tx = tid & 15;
    int ty = tid >> 4;
    int bid = blockIdx.x;

    if (bid < QKVB) {
        int z = bid / 316;
        int b2 = bid - z * 316;
        int row0 = (b2 % 79) * 128;
        int col0 = (b2 / 79) * 128;
        const float* W = (z == 0) ? Wq : (z == 1) ? Wk : Wv;
        const float* bias = (z == 0) ? bq : (z == 1) ? bk : bv;

        ull acc[32];
        gemm_core(A, W, row0, col0, 512, acc, As, Bs);

        int gc = col0 + tx * 8;
        float bvv[8];
        #pragma unroll
        for (int j = 0; j < 8; j++) bvv[j] = bias[gc + j];

        #pragma unroll
        for (int i = 0; i < 8; i++) {
            int gr = row0 + ty * 8 + i;
            if (gr >= Nn) continue;
            float c[8];
            #pragma unroll
            for (int j = 0; j < 4; j++) {
                float2 p = unpack2(acc[i * 4 + j]);
                c[2 * j]     = p.x + bvv[2 * j];
                c[2 * j + 1] = p.y + bvv[2 * j + 1];
            }
            size_t o = (size_t)gr * 512 + gc;
            if (z == 0) {
                *(float4*)(g_q + o)     = make_float4(c[0], c[1], c[2], c[3]);
                *(float4*)(g_q + o + 4) = make_float4(c[4], c[5], c[6], c[7]);
            } else {
                __half2 h0 = __floats2half2_rn(c[0], c[1]);
                __half2 h1 = __floats2half2_rn(c[2], c[3]);
                __half2 h2 = __floats2half2_rn(c[4], c[5]);
                __half2 h3 = __floats2half2_rn(c[6], c[7]);
                uint4 pk = make_uint4(*(unsigned*)&h0, *(unsigned*)&h1,
                                      *(unsigned*)&h2, *(unsigned*)&h3);
                if (z == 1) *(uint4*)(g_kh + o) = pk;
                else        *(uint4*)(g_vh + o) = pk;
            }
        }
    } else {
        int row0 = (bid - QKVB) * 128;

        ull acc[32];
        gemm_core(A, Wsk, row0, 0, 128, acc, As, Bs);

        int gc = tx * 8;
        float bvv[8], scv[8], mnv[8], btv[8];
        #pragma unroll
        for (int j = 0; j < 8; j++) {
            bvv[j] = bsk[gc + j];
            scv[j] = bng[gc + j] * rsqrtf(bnv[gc + j] + 1e-5f);
            mnv[j] = bnm[gc + j];
            btv[j] = bnb[gc + j];
        }

        #pragma unroll
        for (int i = 0; i < 8; i++) {
            int gr = row0 + ty * 8 + i;
            float c[8];
            #pragma unroll
            for (int j = 0; j < 4; j++) {
                float2 p = unpack2(acc[i * 4 + j]);
                c[2 * j]     = p.x + bvv[2 * j];
                c[2 * j + 1] = p.y + bvv[2 * j + 1];
            }
            if (gr >= Nn) {
                #pragma unroll
                for (int j = 0; j < 8; j++)
                    c[j] = fmaxf((c[j] - mnv[j]) * scv[j] + btv[j], 0.f);
            }
            float* dstp = C + (size_t)gr * 128 + gc;
            *(float4*)(dstp)     = make_float4(c[0], c[1], c[2], c[3]);
            *(float4*)(dstp + 4) = make_float4(c[4], c[5], c[6], c[7]);
        }
    }
}

// ================= fused attention (fp16 K/V, 2-way ILP online softmax) =================
__global__ __launch_bounds__(128) void attn_kernel(
    const float* __restrict__ q, const __half* __restrict__ kh,
    const __half* __restrict__ vh, float* __restrict__ hnext,
    const float* __restrict__ bng, const float* __restrict__ bnb,
    const float* __restrict__ bnm, const float* __restrict__ bnv)
{
    int n = blockIdx.x;
    int warp = threadIdx.x >> 5;
    int lane = threadIdx.x & 31;
    __shared__ float outsh[4][128];

    const float4 qr = *(const float4*)(q + (size_t)n * 512 + warp * 128 + lane * 4);
    int b = g_off[n], e = g_off[n + 1];

    float m1 = -1e30f, d1 = 0.f, x10 = 0.f, x11 = 0.f, x12 = 0.f, x13 = 0.f;
    float m2 = -1e30f, d2 = 0.f, x20 = 0.f, x21 = 0.f, x22 = 0.f, x23 = 0.f;

    int ei = b;
    for (; ei + 1 < e; ei += 2) {
        int s1 = g_srcs[ei];
        int s2 = g_srcs[ei + 1];
        size_t base1 = (size_t)s1 * 512 + warp * 128;
        size_t base2 = (size_t)s2 * 512 + warp * 128;
        uint2 kr1 = ((const uint2*)(kh + base1))[lane];
        uint2 kr2 = ((const uint2*)(kh + base2))[lane];
        float2 ka1 = __half22float2(*(const __half2*)&kr1.x);
        float2 kb1 = __half22float2(*(const __half2*)&kr1.y);
        float2 ka2 = __half22float2(*(const __half2*)&kr2.x);
        float2 kb2 = __half22float2(*(const __half2*)&kr2.y);
        float p1 = qr.x * ka1.x + qr.y * ka1.y + qr.z * kb1.x + qr.w * kb1.y;
        float p2 = qr.x * ka2.x + qr.y * ka2.y + qr.z * kb2.x + qr.w * kb2.y;
        #pragma unroll
        for (int o = 16; o; o >>= 1) {
            p1 += __shfl_xor_sync(0xffffffffu, p1, o);
            p2 += __shfl_xor_sync(0xffffffffu, p2, o);
        }
        uint2 vr1 = ((const uint2*)(vh + base1))[lane];
        uint2 vr2 = ((const uint2*)(vh + base2))[lane];
        float a1 = p1 * 0.08838834764831843f;
        float a2 = p2 * 0.08838834764831843f;
        {
            float mn = fmaxf(m1, a1);
            float sc = __expf(m1 - mn);
            float w  = __expf(a1 - mn);
            float2 va = __half22float2(*(const __half2*)&vr1.x);
            float2 vb = __half22float2(*(const __half2*)&vr1.y);
            d1  = d1 * sc + w;
            x10 = x10 * sc + w * va.x;
            x11 = x11 * sc + w * va.y;
            x12 = x12 * sc + w * vb.x;
            x13 = x13 * sc + w * vb.y;
            m1 = mn;
        }
        {
            float mn = fmaxf(m2, a2);
            float sc = __expf(m2 - mn);
            float w  = __expf(a2 - mn);
            float2 va = __half22float2(*(const __half2*)&vr2.x);
            float2 vb = __half22float2(*(const __half2*)&vr2.y);
            d2  = d2 * sc + w;
            x20 = x20 * sc + w * va.x;
            x21 = x21 * sc + w * va.y;
            x22 = x22 * sc + w * vb.x;
            x23 = x23 * sc + w * vb.y;
            m2 = mn;
        }
    }
    if (ei < e) {
        int s = g_srcs[ei];
        size_t base = (size_t)s * 512 + warp * 128;
        uint2 kr = ((const uint2*)(kh + base))[lane];
        float2 ka = __half22float2(*(const __half2*)&kr.x);
        float2 kb = __half22float2(*(const __half2*)&kr.y);
        float p = qr.x * ka.x + qr.y * ka.y + qr.z * kb.x + qr.w * kb.y;
        #pragma unroll
        for (int o = 16; o; o >>= 1) p += __shfl_xor_sync(0xffffffffu, p, o);
        float a = p * 0.08838834764831843f;
        float mn = fmaxf(m1, a);
        float sc = __expf(m1 - mn);
        float w  = __expf(a - mn);
        uint2 vr = ((const uint2*)(vh + base))[lane];
        float2 va = __half22float2(*(const __half2*)&vr.x);
        float2 vb = __half22float2(*(const __half2*)&vr.y);
        d1  = d1 * sc + w;
        x10 = x10 * sc + w * va.x;
        x11 = x11 * sc + w * va.y;
        x12 = x12 * sc + w * vb.x;
        x13 = x13 * sc + w * vb.y;
        m1 = mn;
    }
    {
        float mn = fmaxf(m1, m2);
        float s1 = __expf(m1 - mn);
        float s2 = (d2 > 0.f) ? __expf(m2 - mn) : 0.f;
        d1  = d1 * s1 + d2 * s2;
        x10 = x10 * s1 + x20 * s2;
        x11 = x11 * s1 + x21 * s2;
        x12 = x12 * s1 + x22 * s2;
        x13 = x13 * s1 + x23 * s2;
    }
    float inv = 1.f / (d1 + 1e-16f);
    outsh[warp][lane * 4 + 0] = x10 * inv;
    outsh[warp][lane * 4 + 1] = x11 * inv;
    outsh[warp][lane * 4 + 2] = x12 * inv;
    outsh[warp][lane * 4 + 3] = x13 * inv;
    __syncthreads();

    int t = threadIdx.x;
    float val = hnext[(size_t)n * 128 + t] +
                0.25f * (outsh[0][t] + outsh[1][t] + outsh[2][t] + outsh[3][t]);
    float sc = bng[t] * rsqrtf(bnv[t] + 1e-5f);
    float r = (val - bnm[t]) * sc + bnb[t];
    hnext[(size_t)n * 128 + t] = fmaxf(r, 0.f);
}

// ================= two-stage sort-pool =================
__global__ __launch_bounds__(256) void sp1_kernel(const float* __restrict__ h)
{
    int g = blockIdx.x / 10;
    int part = blockIdx.x % 10;
    int t = threadIdx.x;
    __shared__ unsigned int skey[1000];
    __shared__ ull sbest[256];

    for (int i = t; i < 1000; i += 256) {
        float val = h[((size_t)g * Nn + part * 1000 + i) * 128 + 127];
        unsigned int bits = __float_as_uint(val);
        skey[i] = (bits & 0x80000000u) ? ~bits : (bits | 0x80000000u);
    }
    __syncthreads();

    for (int kk = 0; kk < Kk; kk++) {
        ull best = 0ull;
        for (int i = t; i < 1000; i += 256) {
            ull key = ((ull)skey[i] << 32) |
                      (unsigned int)(0xFFFFFFFFu - (part * 1000 + i));
            if (key > best) best = key;
        }
        sbest[t] = best;
        __syncthreads();
        for (int s = 128; s > 0; s >>= 1) {
            if (t < s) { ull o = sbest[t + s]; if (o > sbest[t]) sbest[t] = o; }
            __syncthreads();
        }
        if (t == 0) {
            ull top = sbest[0];
            int nig = (int)(0xFFFFFFFFu - (unsigned int)(top & 0xFFFFFFFFull));
            g_cand[blockIdx.x * Kk + kk] = top;
            skey[nig - part * 1000] = 0;
        }
        __syncthreads();
    }
}

__global__ __launch_bounds__(256) void sp2_kernel(const float* __restrict__ h,
                                                  const float* __restrict__ age)
{
    int g = blockIdx.x;
    int t = threadIdx.x;
    __shared__ ull cand[300];
    __shared__ ull sbest[256];

    for (int i = t; i < 300; i += 256) cand[i] = g_cand[g * 300 + i];
    __syncthreads();

    for (int kk = 0; kk < Kk; kk++) {
        ull best = 0ull;
        for (int i = t; i < 300; i += 256) { ull k = cand[i]; if (k > best) best = k; }
        sbest[t] = best;
        __syncthreads();
        for (int s = 128; s > 0; s >>= 1) {
            if (t < s) { ull o = sbest[t + s]; if (o > sbest[t]) sbest[t] = o; }
            __syncthreads();
        }
        ull top = sbest[0];
        if (t == 0) {
            int nig = (int)(0xFFFFFFFFu - (unsigned int)(top & 0xFFFFFFFFull));
            g_topk[g * Kk + kk] = nig;
        }
        __syncthreads();
        for (int i = t; i < 300; i += 256) if (cand[i] == top) cand[i] = 0;
        __syncthreads();
    }

    for (int i = t; i < Kk * 128; i += 256) {
        int kkk = i >> 7, c = i & 127;
        int n = g_topk[g * Kk + kkk];
        g_z[g * ZLEN + i] = h[((size_t)g * Nn + n) * 128 + c];
    }
    if (t == 0) g_z[g * ZLEN + Kk * 128] = age[g];
}

// ================= MLP head, stage 1: hid[g, 512] over 64 blocks =================
__global__ __launch_bounds__(256) void mlp1_kernel(
    const float* __restrict__ W1, const float* __restrict__ b1)
{
    int seg = blockIdx.x;   // 0..7 -> 64 hidden cols
    int g   = blockIdx.y;   // 0..7 graph
    int t = threadIdx.x;
    __shared__ float zs[ZLEN];
    __shared__ float red[4][64];

    for (int i = t; i < ZLEN; i += 256) zs[i] = g_z[g * ZLEN + i];
    __syncthreads();

    int u = t & 63;
    int p = t >> 6;
    int col = seg * 64 + u;
    int j0 = p * 960;
    int j1 = (p == 3) ? ZLEN : (j0 + 960);
    float acc = 0.f;
    for (int j = j0; j < j1; j++) acc += zs[j] * W1[(size_t)j * 512 + col];
    red[p][u] = acc;
    __syncthreads();
    if (t < 64) {
        float s = red[0][t] + red[1][t] + red[2][t] + red[3][t] + b1[seg * 64 + t];
        g_hid[g * 512 + seg * 64 + t] = fmaxf(s, 0.f);
    }
}

// ================= MLP head, stage 2: logits + log-softmax =================
__global__ __launch_bounds__(512) void mlp2_kernel(
    const float* __restrict__ W2, const float* __restrict__ b2,
    float* __restrict__ out)
{
    int g = blockIdx.x;
    int t = threadIdx.x;
    __shared__ float red0[512];
    __shared__ float red1[512];

    float hid = g_hid[g * 512 + t];
    red0[t] = hid * W2[t * 2 + 0];
    red1[t] = hid * W2[t * 2 + 1];
    __syncthreads();
    for (int s = 256; s > 0; s >>= 1) {
        if (t < s) { red0[t] += red0[t + s]; red1[t] += red1[t + s]; }
        __syncthreads();
    }
    if (t == 0) {
        float o0 = red0[0] + b2[0];
        float o1 = red1[0] + b2[1];
        float mx = fmaxf(o0, o1);
        float lse = mx + logf(expf(o0 - mx) + expf(o1 - mx));
        out[g * 2 + 0] = o0 - lse;
        out[g * 2 + 1] = o1 - lse;
    }
}

// ================= launch =================
extern "C" void kernel_launch(void* const* d_in, const int* in_sizes, int n_in,
                              void* d_out, int out_size)
{
    const float* x     = (const float*)d_in[0];
    const int*   eidx  = (const int*)  d_in[1];
    const float* age   = (const float*)d_in[2];
    const float* Wq    = (const float*)d_in[3];
    const float* bq    = (const float*)d_in[4];
    const float* Wk    = (const float*)d_in[5];
    const float* bk    = (const float*)d_in[6];
    const float* Wv    = (const float*)d_in[7];
    const float* bv    = (const float*)d_in[8];
    const float* Wsk   = (const float*)d_in[9];
    const float* bsk   = (const float*)d_in[10];
    const float* bn_g  = (const float*)d_in[11];
    const float* bn_b  = (const float*)d_in[12];
    const float* bn_m  = (const float*)d_in[13];
    const float* bn_v  = (const float*)d_in[14];
    const float* W1    = (const float*)d_in[15];
    const float* b1    = (const float*)d_in[16];
    const float* W2    = (const float*)d_in[17];
    const float* b2    = (const float*)d_in[18];
    float* out = (float*)d_out;

    int E = in_sizes[1] / 2;
    const int* src = eidx;
    const int* dst = eidx + E;

    float *q, *hA, *hB;
    __half *kh, *vh;
    cudaGetSymbolAddress((void**)&q,  g_q);
    cudaGetSymbolAddress((void**)&kh, g_kh);
    cudaGetSymbolAddress((void**)&vh, g_vh);
    cudaGetSymbolAddress((void**)&hA, g_hA);
    cudaGetSymbolAddress((void**)&hB, g_hB);

    // CSR build
    zero_deg_kernel<<<(Nn + 256) / 256, 256>>>();
    hist_kernel<<<(E + 255) / 256, 256>>>(dst, E);
    scan_kernel<<<1, 1024>>>();
    scatter_kernel<<<(E + 255) / 256, 256>>>(src, dst, E);

    const float* hcur = x;
    float* hnext = hA;
    for (int l = 0; l < 3; l++) {
        gemm_kernel<<<GEMMB, 256>>>(hcur, Wq, bq, Wk, bk, Wv, bv, Wsk, bsk, hnext,
                                    bn_g + l * 128, bn_b + l * 128,
                                    bn_m + l * 128, bn_v + l * 128);
        attn_kernel<<<Nn, 128>>>(q, kh, vh, hnext,
                                 bn_g + l * 128, bn_b + l * 128,
                                 bn_m + l * 128, bn_v + l * 128);
        hcur = hnext;
        hnext = (hcur == hA) ? hB : hA;
    }

    sp1_kernel<<<80, 256>>>(hcur);
    sp2_kernel<<<Bg, 256>>>(hcur, age);
    mlp1_kernel<<<dim3(8, Bg), 256>>>(W1, b1);
    mlp2_kernel<<<Bg, 512>>>(W2, b2, out);
}

// round 16
// speedup vs baseline: 1.4824x; 1.0363x over previous
#include <cuda_runtime.h>
#include <cuda_fp16.h>
#include <cstdint>
#include <math.h>

typedef unsigned long long ull;

// ---- static problem config ----
#define Nn    10000
#define NTOTc 80000
#define Bg    8
#define Emax  320000
#define Kk    30
#define ZLEN  3841           // K*C + 1

// fused GEMM launch: 948 qkv tiles (3 x 316) + 625 skip tiles
#define QKVB  948
#define GEMMB 1573

// ---- scratch ----
__device__ float  g_q[Nn * 512];
__device__ __half g_kh[Nn * 512];
__device__ __half g_vh[Nn * 512];
__device__ float  g_hA[(size_t)NTOTc * 128];
__device__ float  g_hB[(size_t)NTOTc * 128];
__device__ int    g_deg[Nn + 1];
__device__ int    g_off[Nn + 1];
__device__ int    g_cur[Nn];
__device__ int    g_srcs[Emax];
__device__ ull    g_cand[80 * Kk];
__device__ float  g_z[Bg * ZLEN];
__device__ int    g_topk[Bg * Kk];
__device__ float  g_hidp[8 * Bg * 512];   // [kpart][g][col]

// ---- packed f32x2 helpers ----
static __device__ __forceinline__ ull pack2(float lo, float hi) {
    ull d; asm("mov.b64 %0, {%1, %2};" : "=l"(d) : "f"(lo), "f"(hi)); return d;
}
static __device__ __forceinline__ ull fma2(ull a, ull b, ull c) {
    ull d; asm("fma.rn.f32x2 %0, %1, %2, %3;" : "=l"(d) : "l"(a), "l"(b), "l"(c)); return d;
}
static __device__ __forceinline__ float2 unpack2(ull d) {
    float2 f; asm("mov.b64 {%0, %1}, %2;" : "=f"(f.x), "=f"(f.y) : "l"(d)); return f;
}

// ================= CSR build =================
__global__ void zero_deg_kernel() {
    int i = blockIdx.x * blockDim.x + threadIdx.x;
    if (i <= Nn) g_deg[i] = 0;
}
__global__ void hist_kernel(const int* __restrict__ dst, int E) {
    int e = blockIdx.x * blockDim.x + threadIdx.x;
    if (e < E) atomicAdd(&g_deg[dst[e]], 1);
}
__global__ __launch_bounds__(1024) void scan_kernel() {
    __shared__ int partial[1024];
    const int PER = 10;
    int t = threadIdx.x;
    int base = t * PER;
    int local[PER];
    int s = 0;
    #pragma unroll
    for (int i = 0; i < PER; i++) {
        int idx = base + i;
        int dv = (idx < Nn) ? g_deg[idx] : 0;
        local[i] = s; s += dv;
    }
    partial[t] = s;
    __syncthreads();
    for (int offd = 1; offd < 1024; offd <<= 1) {
        int addv = 0;
        if (t >= offd) addv = partial[t - offd];
        __syncthreads();
        if (t >= offd) partial[t] += addv;
        __syncthreads();
    }
    int pre = (t > 0) ? partial[t - 1] : 0;
    #pragma unroll
    for (int i = 0; i < PER; i++) {
        int idx = base + i;
        if (idx < Nn) { int o = pre + local[i]; g_off[idx] = o; g_cur[idx] = o; }
    }
    if (t == 1023) g_off[Nn] = partial[1023];
}
__global__ void scatter_kernel(const int* __restrict__ src,
                               const int* __restrict__ dst, int E) {
    int e = blockIdx.x * blockDim.x + threadIdx.x;
    if (e < E) {
        int d = dst[e];
        int p = atomicAdd(&g_cur[d], 1);
        g_srcs[p] = src[e];
    }
}

// ================= f32x2 GEMM core, double-buffered (1 sync/chunk) =================
static __device__ __forceinline__ void gemm_core(
    const float* __restrict__ A, const float* __restrict__ W,
    int row0, int col0, int Nout, ull* acc,
    float (*As)[16][132], float (*Bs)[16][132])
{
    int tid = threadIdx.x;
    int tx = tid & 15;
    int ty = tid >> 4;

    #pragma unroll
    for (int i = 0; i < 32; i++) acc[i] = 0ull;

    int rA[2], kqA[2], sr[2];
    float4 pa[2], pb[2];
    #pragma unroll
    for (int i = 0; i < 2; i++) {
        int f = tid + i * 256;
        int rr = row0 + (f >> 2);
        rA[i] = (rr < NTOTc) ? rr : (NTOTc - 1);
        sr[i] = f >> 2;
        kqA[i] = (f & 3) * 4;
        pa[i] = *(const float4*)(A + (size_t)rA[i] * 128 + kqA[i]);
    }
    int kB = tid >> 4;
    int nB = (tid & 15) * 8;
    pb[0] = *(const float4*)(W + (size_t)kB * Nout + col0 + nB);
    pb[1] = *(const float4*)(W + (size_t)kB * Nout + col0 + nB + 4);

    #pragma unroll
    for (int i = 0; i < 2; i++) {
        As[0][kqA[i] + 0][sr[i]] = pa[i].x;
        As[0][kqA[i] + 1][sr[i]] = pa[i].y;
        As[0][kqA[i] + 2][sr[i]] = pa[i].z;
        As[0][kqA[i] + 3][sr[i]] = pa[i].w;
    }
    *(float4*)&Bs[0][kB][nB]     = pb[0];
    *(float4*)&Bs[0][kB][nB + 4] = pb[1];
    __syncthreads();

    #pragma unroll
    for (int kc = 0; kc < 8; kc++) {
        int cur = kc & 1;
        int nxt = cur ^ 1;
        if (kc < 7) {
            int k0n = (kc + 1) * 16;
            #pragma unroll
            for (int i = 0; i < 2; i++)
                pa[i] = *(const float4*)(A + (size_t)rA[i] * 128 + k0n + kqA[i]);
            pb[0] = *(const float4*)(W + (size_t)(k0n + kB) * Nout + col0 + nB);
            pb[1] = *(const float4*)(W + (size_t)(k0n + kB) * Nout + col0 + nB + 4);
        }
        #pragma unroll
        for (int k = 0; k < 16; k++) {
            float4 a0 = *(const float4*)&As[cur][k][ty * 8];
            float4 a1 = *(const float4*)&As[cur][k][ty * 8 + 4];
            const ull* bp = (const ull*)&Bs[cur][k][tx * 8];
            ull b0 = bp[0], b1 = bp[1], b2 = bp[2], b3 = bp[3];
            ull ad[8];
            ad[0] = pack2(a0.x, a0.x); ad[1] = pack2(a0.y, a0.y);
            ad[2] = pack2(a0.z, a0.z); ad[3] = pack2(a0.w, a0.w);
            ad[4] = pack2(a1.x, a1.x); ad[5] = pack2(a1.y, a1.y);
            ad[6] = pack2(a1.z, a1.z); ad[7] = pack2(a1.w, a1.w);
            #pragma unroll
            for (int i = 0; i < 8; i++) {
                acc[i * 4 + 0] = fma2(ad[i], b0, acc[i * 4 + 0]);
                acc[i * 4 + 1] = fma2(ad[i], b1, acc[i * 4 + 1]);
                acc[i * 4 + 2] = fma2(ad[i], b2, acc[i * 4 + 2]);
                acc[i * 4 + 3] = fma2(ad[i], b3, acc[i * 4 + 3]);
            }
        }
        if (kc < 7) {
            #pragma unroll
            for (int i = 0; i < 2; i++) {
                As[nxt][kqA[i] + 0][sr[i]] = pa[i].x;
                As[nxt][kqA[i] + 1][sr[i]] = pa[i].y;
                As[nxt][kqA[i] + 2][sr[i]] = pa[i].z;
                As[nxt][kqA[i] + 3][sr[i]] = pa[i].w;
            }
            *(float4*)&Bs[nxt][kB][nB]     = pb[0];
            *(float4*)&Bs[nxt][kB][nB + 4] = pb[1];
        }
        __syncthreads();
    }
}

// ================= fused GEMM launch: qkv (0..947) | skip (948..1572) =================
__global__ __launch_bounds__(256, 2) void gemm_kernel(
    const float* __restrict__ A,
    const float* __restrict__ Wq, const float* __restrict__ bq,
    const float* __restrict__ Wk, const float* __restrict__ bk,
    const float* __restrict__ Wv, const float* __restrict__ bv,
    const float* __restrict__ Wsk, const float* __restrict__ bsk,
    float* __restrict__ C,
    const float* __restrict__ bng, const float* __restrict__ bnb,
    const float* __restrict__ bnm, const float* __restrict__ bnv)
{
    __shared__ __align__(16) float As[2][16][132];
    __shared__ __align__(16) float Bs[2][16][132];
    int tid = threadIdx.x;
    int tx = tid & 15;
    int ty = tid >> 4;
    int bid = blockIdx.x;

    if (bid < QKVB) {
        int z = bid / 316;
        int b2 = bid - z * 316;
        int row0 = (b2 % 79) * 128;
        int col0 = (b2 / 79) * 128;
        const float* W = (z == 0) ? Wq : (z == 1) ? Wk : Wv;
        const float* bias = (z == 0) ? bq : (z == 1) ? bk : bv;

        ull acc[32];
        gemm_core(A, W, row0, col0, 512, acc, As, Bs);

        int gc = col0 + tx * 8;
        float bvv[8];
        #pragma unroll
        for (int j = 0; j < 8; j++) bvv[j] = bias[gc + j];

        #pragma unroll
        for (int i = 0; i < 8; i++) {
            int gr = row0 + ty * 8 + i;
            if (gr >= Nn) continue;
            float c[8];
            #pragma unroll
            for (int j = 0; j < 4; j++) {
                float2 p = unpack2(acc[i * 4 + j]);
                c[2 * j]     = p.x + bvv[2 * j];
                c[2 * j + 1] = p.y + bvv[2 * j + 1];
            }
            size_t o = (size_t)gr * 512 + gc;
            if (z == 0) {
                *(float4*)(g_q + o)     = make_float4(c[0], c[1], c[2], c[3]);
                *(float4*)(g_q + o + 4) = make_float4(c[4], c[5], c[6], c[7]);
            } else {
                __half2 h0 = __floats2half2_rn(c[0], c[1]);
                __half2 h1 = __floats2half2_rn(c[2], c[3]);
                __half2 h2 = __floats2half2_rn(c[4], c[5]);
                __half2 h3 = __floats2half2_rn(c[6], c[7]);
                uint4 pk = make_uint4(*(unsigned*)&h0, *(unsigned*)&h1,
                                      *(unsigned*)&h2, *(unsigned*)&h3);
                if (z == 1) *(uint4*)(g_kh + o) = pk;
                else        *(uint4*)(g_vh + o) = pk;
            }
        }
    } else {
        int row0 = (bid - QKVB) * 128;

        ull acc[32];
        gemm_core(A, Wsk, row0, 0, 128, acc, As, Bs);

        int gc = tx * 8;
        float bvv[8], scv[8], mnv[8], btv[8];
        #pragma unroll
        for (int j = 0; j < 8; j++) {
            bvv[j] = bsk[gc + j];
            scv[j] = bng[gc + j] * rsqrtf(bnv[gc + j] + 1e-5f);
            mnv[j] = bnm[gc + j];
            btv[j] = bnb[gc + j];
        }

        #pragma unroll
        for (int i = 0; i < 8; i++) {
            int gr = row0 + ty * 8 + i;
            float c[8];
            #pragma unroll
            for (int j = 0; j < 4; j++) {
                float2 p = unpack2(acc[i * 4 + j]);
                c[2 * j]     = p.x + bvv[2 * j];
                c[2 * j + 1] = p.y + bvv[2 * j + 1];
            }
            if (gr >= Nn) {
                #pragma unroll
                for (int j = 0; j < 8; j++)
                    c[j] = fmaxf((c[j] - mnv[j]) * scv[j] + btv[j], 0.f);
            }
            float* dstp = C + (size_t)gr * 128 + gc;
            *(float4*)(dstp)     = make_float4(c[0], c[1], c[2], c[3]);
            *(float4*)(dstp + 4) = make_float4(c[4], c[5], c[6], c[7]);
        }
    }
}

// ================= fused attention (fp16 K/V, 2-way ILP online softmax) =================
__global__ __launch_bounds__(128) void attn_kernel(
    const float* __restrict__ q, const __half* __restrict__ kh,
    const __half* __restrict__ vh, float* __restrict__ hnext,
    const float* __restrict__ bng, const float* __restrict__ bnb,
    const float* __restrict__ bnm, const float* __restrict__ bnv)
{
    int n = blockIdx.x;
    int warp = threadIdx.x >> 5;
    int lane = threadIdx.x & 31;
    __shared__ float outsh[4][128];

    const float4 qr = *(const float4*)(q + (size_t)n * 512 + warp * 128 + lane * 4);
    int b = g_off[n], e = g_off[n + 1];

    float m1 = -1e30f, d1 = 0.f, x10 = 0.f, x11 = 0.f, x12 = 0.f, x13 = 0.f;
    float m2 = -1e30f, d2 = 0.f, x20 = 0.f, x21 = 0.f, x22 = 0.f, x23 = 0.f;

    int ei = b;
    for (; ei + 1 < e; ei += 2) {
        int s1 = g_srcs[ei];
        int s2 = g_srcs[ei + 1];
        size_t base1 = (size_t)s1 * 512 + warp * 128;
        size_t base2 = (size_t)s2 * 512 + warp * 128;
        uint2 kr1 = ((const uint2*)(kh + base1))[lane];
        uint2 kr2 = ((const uint2*)(kh + base2))[lane];
        float2 ka1 = __half22float2(*(const __half2*)&kr1.x);
        float2 kb1 = __half22float2(*(const __half2*)&kr1.y);
        float2 ka2 = __half22float2(*(const __half2*)&kr2.x);
        float2 kb2 = __half22float2(*(const __half2*)&kr2.y);
        float p1 = qr.x * ka1.x + qr.y * ka1.y + qr.z * kb1.x + qr.w * kb1.y;
        float p2 = qr.x * ka2.x + qr.y * ka2.y + qr.z * kb2.x + qr.w * kb2.y;
        #pragma unroll
        for (int o = 16; o; o >>= 1) {
            p1 += __shfl_xor_sync(0xffffffffu, p1, o);
            p2 += __shfl_xor_sync(0xffffffffu, p2, o);
        }
        uint2 vr1 = ((const uint2*)(vh + base1))[lane];
        uint2 vr2 = ((const uint2*)(vh + base2))[lane];
        float a1 = p1 * 0.08838834764831843f;
        float a2 = p2 * 0.08838834764831843f;
        {
            float mn = fmaxf(m1, a1);
            float sc = __expf(m1 - mn);
            float w  = __expf(a1 - mn);
            float2 va = __half22float2(*(const __half2*)&vr1.x);
            float2 vb = __half22float2(*(const __half2*)&vr1.y);
            d1  = d1 * sc + w;
            x10 = x10 * sc + w * va.x;
            x11 = x11 * sc + w * va.y;
            x12 = x12 * sc + w * vb.x;
            x13 = x13 * sc + w * vb.y;
            m1 = mn;
        }
        {
            float mn = fmaxf(m2, a2);
            float sc = __expf(m2 - mn);
            float w  = __expf(a2 - mn);
            float2 va = __half22float2(*(const __half2*)&vr2.x);
            float2 vb = __half22float2(*(const __half2*)&vr2.y);
            d2  = d2 * sc + w;
            x20 = x20 * sc + w * va.x;
            x21 = x21 * sc + w * va.y;
            x22 = x22 * sc + w * vb.x;
            x23 = x23 * sc + w * vb.y;
            m2 = mn;
        }
    }
    if (ei < e) {
        int s = g_srcs[ei];
        size_t base = (size_t)s * 512 + warp * 128;
        uint2 kr = ((const uint2*)(kh + base))[lane];
        float2 ka = __half22float2(*(const __half2*)&kr.x);
        float2 kb = __half22float2(*(const __half2*)&kr.y);
        float p = qr.x * ka.x + qr.y * ka.y + qr.z * kb.x + qr.w * kb.y;
        #pragma unroll
        for (int o = 16; o; o >>= 1) p += __shfl_xor_sync(0xffffffffu, p, o);
        float a = p * 0.08838834764831843f;
        float mn = fmaxf(m1, a);
        float sc = __expf(m1 - mn);
        float w  = __expf(a - mn);
        uint2 vr = ((const uint2*)(vh + base))[lane];
        float2 va = __half22float2(*(const __half2*)&vr.x);
        float2 vb = __half22float2(*(const __half2*)&vr.y);
        d1  = d1 * sc + w;
        x10 = x10 * sc + w * va.x;
        x11 = x11 * sc + w * va.y;
        x12 = x12 * sc + w * vb.x;
        x13 = x13 * sc + w * vb.y;
        m1 = mn;
    }
    {
        float mn = fmaxf(m1, m2);
        float s1 = __expf(m1 - mn);
        float s2 = (d2 > 0.f) ? __expf(m2 - mn) : 0.f;
        d1  = d1 * s1 + d2 * s2;
        x10 = x10 * s1 + x20 * s2;
        x11 = x11 * s1 + x21 * s2;
        x12 = x12 * s1 + x22 * s2;
        x13 = x13 * s1 + x23 * s2;
    }
    float inv = 1.f / (d1 + 1e-16f);
    outsh[warp][lane * 4 + 0] = x10 * inv;
    outsh[warp][lane * 4 + 1] = x11 * inv;
    outsh[warp][lane * 4 + 2] = x12 * inv;
    outsh[warp][lane * 4 + 3] = x13 * inv;
    __syncthreads();

    int t = threadIdx.x;
    float val = hnext[(size_t)n * 128 + t] +
                0.25f * (outsh[0][t] + outsh[1][t] + outsh[2][t] + outsh[3][t]);
    float sc = bng[t] * rsqrtf(bnv[t] + 1e-5f);
    float r = (val - bnm[t]) * sc + bnb[t];
    hnext[(size_t)n * 128 + t] = fmaxf(r, 0.f);
}

// ================= two-stage sort-pool =================
__global__ __launch_bounds__(256) void sp1_kernel(const float* __restrict__ h)
{
    int g = blockIdx.x / 10;
    int part = blockIdx.x % 10;
    int t = threadIdx.x;
    __shared__ unsigned int skey[1000];
    __shared__ ull sbest[256];

    for (int i = t; i < 1000; i += 256) {
        float val = h[((size_t)g * Nn + part * 1000 + i) * 128 + 127];
        unsigned int bits = __float_as_uint(val);
        skey[i] = (bits & 0x80000000u) ? ~bits : (bits | 0x80000000u);
    }
    __syncthreads();

    for (int kk = 0; kk < Kk; kk++) {
        ull best = 0ull;
        for (int i = t; i < 1000; i += 256) {
            ull key = ((ull)skey[i] << 32) |
                      (unsigned int)(0xFFFFFFFFu - (part * 1000 + i));
            if (key > best) best = key;
        }
        sbest[t] = best;
        __syncthreads();
        for (int s = 128; s > 0; s >>= 1) {
            if (t < s) { ull o = sbest[t + s]; if (o > sbest[t]) sbest[t] = o; }
            __syncthreads();
        }
        if (t == 0) {
            ull top = sbest[0];
            int nig = (int)(0xFFFFFFFFu - (unsigned int)(top & 0xFFFFFFFFull));
            g_cand[blockIdx.x * Kk + kk] = top;
            skey[nig - part * 1000] = 0;
        }
        __syncthreads();
    }
}

__global__ __launch_bounds__(256) void sp2_kernel(const float* __restrict__ h,
                                                  const float* __restrict__ age)
{
    int g = blockIdx.x;
    int t = threadIdx.x;
    __shared__ ull cand[300];
    __shared__ ull sbest[256];

    for (int i = t; i < 300; i += 256) cand[i] = g_cand[g * 300 + i];
    __syncthreads();

    for (int kk = 0; kk < Kk; kk++) {
        ull best = 0ull;
        for (int i = t; i < 300; i += 256) { ull k = cand[i]; if (k > best) best = k; }
        sbest[t] = best;
        __syncthreads();
        for (int s = 128; s > 0; s >>= 1) {
            if (t < s) { ull o = sbest[t + s]; if (o > sbest[t]) sbest[t] = o; }
            __syncthreads();
        }
        ull top = sbest[0];
        if (t == 0) {
            int nig = (int)(0xFFFFFFFFu - (unsigned int)(top & 0xFFFFFFFFull));
            g_topk[g * Kk + kk] = nig;
        }
        __syncthreads();
        for (int i = t; i < 300; i += 256) if (cand[i] == top) cand[i] = 0;
        __syncthreads();
    }

    for (int i = t; i < Kk * 128; i += 256) {
        int kkk = i >> 7, c = i & 127;
        int n = g_topk[g * Kk + kkk];
        g_z[g * ZLEN + i] = h[((size_t)g * Nn + n) * 128 + c];
    }
    if (t == 0) g_z[g * ZLEN + Kk * 128] = age[g];
}

// ================= MLP stage 1: W1 read ONCE; partials per (kpart, graph, col) ========
// grid (8 seg, 8 kpart), 256 threads. Each block covers 64 cols x ~480 K x all 8 graphs.
__global__ __launch_bounds__(256) void mlp1_kernel(const float* __restrict__ W1)
{
    int seg = blockIdx.x;     // 64-col segment
    int kp  = blockIdx.y;     // K partition
    int t = threadIdx.x;
    __shared__ float zs[Bg][481];
    __shared__ float red[4][64][8];

    int j0 = kp * 480;
    int j1 = (kp == 7) ? ZLEN : (j0 + 480);
    int len = j1 - j0;

    for (int i = t; i < Bg * len; i += 256) {
        int g = i / len, j = i % len;
        zs[g][j] = g_z[g * ZLEN + j0 + j];
    }
    __syncthreads();

    int u = t & 63;           // col within segment
    int p = t >> 6;           // sub-partition 0..3
    int col = seg * 64 + u;
    int jb = p * (len >> 2);
    int je = (p == 3) ? len : (jb + (len >> 2));

    float acc[8];
    #pragma unroll
    for (int g = 0; g < 8; g++) acc[g] = 0.f;
    for (int j = jb; j < je; j++) {
        float w = W1[(size_t)(j0 + j) * 512 + col];
        #pragma unroll
        for (int g = 0; g < 8; g++) acc[g] += zs[g][j] * w;
    }
    #pragma unroll
    for (int g = 0; g < 8; g++) red[p][u][g] = acc[g];
    __syncthreads();

    // 256 threads = 64 cols x 4... reduce: thread (u, g2) handles 2 graphs
    if (t < 256) {
        int uu = t & 63;
        int gpair = t >> 6;   // 0..3 -> graphs 2*gpair, 2*gpair+1
        #pragma unroll
        for (int h = 0; h < 2; h++) {
            int g = gpair * 2 + h;
            float s = red[0][uu][g] + red[1][uu][g] + red[2][uu][g] + red[3][uu][g];
            g_hidp[(kp * Bg + g) * 512 + seg * 64 + uu] = s;
        }
    }
}

// ================= MLP stage 2: sum partials + bias + relu + logits ================
__global__ __launch_bounds__(512) void mlp2_kernel(
    const float* __restrict__ b1,
    const float* __restrict__ W2, const float* __restrict__ b2,
    float* __restrict__ out)
{
    int g = blockIdx.x;
    int t = threadIdx.x;
    __shared__ float red0[512];
    __shared__ float red1[512];

    float s = b1[t];
    #pragma unroll
    for (int kp = 0; kp < 8; kp++) s += g_hidp[(kp * Bg + g) * 512 + t];
    float hid = fmaxf(s, 0.f);

    red0[t] = hid * W2[t * 2 + 0];
    red1[t] = hid * W2[t * 2 + 1];
    __syncthreads();
    for (int st = 256; st > 0; st >>= 1) {
        if (t < st) { red0[t] += red0[t + st]; red1[t] += red1[t + st]; }
        __syncthreads();
    }
    if (t == 0) {
        float o0 = red0[0] + b2[0];
        float o1 = red1[0] + b2[1];
        float mx = fmaxf(o0, o1);
        float lse = mx + logf(expf(o0 - mx) + expf(o1 - mx));
        out[g * 2 + 0] = o0 - lse;
        out[g * 2 + 1] = o1 - lse;
    }
}

// ================= launch =================
extern "C" void kernel_launch(void* const* d_in, const int* in_sizes, int n_in,
                              void* d_out, int out_size)
{
    const float* x     = (const float*)d_in[0];
    const int*   eidx  = (const int*)  d_in[1];
    const float* age   = (const float*)d_in[2];
    const float* Wq    = (const float*)d_in[3];
    const float* bq    = (const float*)d_in[4];
    const float* Wk    = (const float*)d_in[5];
    const float* bk    = (const float*)d_in[6];
    const float* Wv    = (const float*)d_in[7];
    const float* bv    = (const float*)d_in[8];
    const float* Wsk   = (const float*)d_in[9];
    const float* bsk   = (const float*)d_in[10];
    const float* bn_g  = (const float*)d_in[11];
    const float* bn_b  = (const float*)d_in[12];
    const float* bn_m  = (const float*)d_in[13];
    const float* bn_v  = (const float*)d_in[14];
    const float* W1    = (const float*)d_in[15];
    const float* b1    = (const float*)d_in[16];
    const float* W2    = (const float*)d_in[17];
    const float* b2    = (const float*)d_in[18];
    float* out = (float*)d_out;

    int E = in_sizes[1] / 2;
    const int* src = eidx;
    const int* dst = eidx + E;

    float *q, *hA, *hB;
    __half *kh, *vh;
    cudaGetSymbolAddress((void**)&q,  g_q);
    cudaGetSymbolAddress((void**)&kh, g_kh);
    cudaGetSymbolAddress((void**)&vh, g_vh);
    cudaGetSymbolAddress((void**)&hA, g_hA);
    cudaGetSymbolAddress((void**)&hB, g_hB);

    // CSR build
    zero_deg_kernel<<<(Nn + 256) / 256, 256>>>();
    hist_kernel<<<(E + 255) / 256, 256>>>(dst, E);
    scan_kernel<<<1, 1024>>>();
    scatter_kernel<<<(E + 255) / 256, 256>>>(src, dst, E);

    const float* hcur = x;
    float* hnext = hA;
    for (int l = 0; l < 3; l++) {
        gemm_kernel<<<GEMMB, 256>>>(hcur, Wq, bq, Wk, bk, Wv, bv, Wsk, bsk, hnext,
                                    bn_g + l * 128, bn_b + l * 128,
                                    bn_m + l * 128, bn_v + l * 128);
        attn_kernel<<<Nn, 128>>>(q, kh, vh, hnext,
                                 bn_g + l * 128, bn_b + l * 128,
                                 bn_m + l * 128, bn_v + l * 128);
        hcur = hnext;
        hnext = (hcur == hA) ? hB : hA;
    }

    sp1_kernel<<<80, 256>>>(hcur);
    sp2_kernel<<<Bg, 256>>>(hcur, age);
    mlp1_kernel<<<dim3(8, 8), 256>>>(W1);
    mlp2_kernel<<<Bg, 512>>>(b1, W2, b2, out);
}

// round 17
// speedup vs baseline: 1.5160x; 1.0226x over previous
#include <cuda_runtime.h>
#include <cuda_fp16.h>
#include <cstdint>
#include <math.h>

typedef unsigned long long ull;

// ---- static problem config ----
#define Nn    10000
#define NTOTc 80000
#define Bg    8
#define Emax  320000
#define Kk    30
#define ZLEN  3841           // K*C + 1

// fused GEMM launch: 948 qkv tiles (3 x 316) + 625 skip tiles
#define QKVB  948
#define GEMMB 1573

// ---- scratch ----
__device__ float  g_q[Nn * 512];
__device__ __half g_kh[Nn * 512];
__device__ __half g_vh[Nn * 512];
__device__ float  g_hA[(size_t)NTOTc * 128];
__device__ float  g_hB[(size_t)NTOTc * 128];
__device__ int    g_deg[Nn + 1];
__device__ int    g_off[Nn + 1];
__device__ int    g_cur[Nn];
__device__ int    g_srcs[Emax];
__device__ ull    g_cand[80 * Kk];
__device__ float  g_z[Bg * ZLEN];
__device__ int    g_topk[Bg * Kk];
__device__ float  g_hidp[8 * Bg * 512];   // [kpart][g][col]

// ---- packed f32x2 helpers ----
static __device__ __forceinline__ ull pack2(float lo, float hi) {
    ull d; asm("mov.b64 %0, {%1, %2};" : "=l"(d) : "f"(lo), "f"(hi)); return d;
}
static __device__ __forceinline__ ull fma2(ull a, ull b, ull c) {
    ull d; asm("fma.rn.f32x2 %0, %1, %2, %3;" : "=l"(d) : "l"(a), "l"(b), "l"(c)); return d;
}
static __device__ __forceinline__ float2 unpack2(ull d) {
    float2 f; asm("mov.b64 {%0, %1}, %2;" : "=f"(f.x), "=f"(f.y) : "l"(d)); return f;
}
static __device__ __forceinline__ ull maxu64(ull a, ull b) { return a > b ? a : b; }

// ================= CSR build =================
__global__ void hist_kernel(const int* __restrict__ dst, int E) {
    int e = blockIdx.x * blockDim.x + threadIdx.x;
    if (e < E) atomicAdd(&g_deg[dst[e]], 1);
}
__global__ __launch_bounds__(1024) void scan_kernel() {
    __shared__ int partial[1024];
    const int PER = 10;
    int t = threadIdx.x;
    int base = t * PER;
    int local[PER];
    int s = 0;
    #pragma unroll
    for (int i = 0; i < PER; i++) {
        int idx = base + i;
        int dv = (idx < Nn) ? g_deg[idx] : 0;
        local[i] = s; s += dv;
    }
    partial[t] = s;
    __syncthreads();
    for (int offd = 1; offd < 1024; offd <<= 1) {
        int addv = 0;
        if (t >= offd) addv = partial[t - offd];
        __syncthreads();
        if (t >= offd) partial[t] += addv;
        __syncthreads();
    }
    int pre = (t > 0) ? partial[t - 1] : 0;
    #pragma unroll
    for (int i = 0; i < PER; i++) {
        int idx = base + i;
        if (idx < Nn) { int o = pre + local[i]; g_off[idx] = o; g_cur[idx] = o; }
    }
    if (t == 1023) g_off[Nn] = partial[1023];
}
__global__ void scatter_kernel(const int* __restrict__ src,
                               const int* __restrict__ dst, int E) {
    int e = blockIdx.x * blockDim.x + threadIdx.x;
    if (e < E) {
        int d = dst[e];
        int p = atomicAdd(&g_cur[d], 1);
        g_srcs[p] = src[e];
    }
}

// ================= f32x2 GEMM core, double-buffered (1 sync/chunk) =================
static __device__ __forceinline__ void gemm_core(
    const float* __restrict__ A, const float* __restrict__ W,
    int row0, int col0, int Nout, ull* acc,
    float (*As)[16][132], float (*Bs)[16][132])
{
    int tid = threadIdx.x;
    int tx = tid & 15;
    int ty = tid >> 4;

    #pragma unroll
    for (int i = 0; i < 32; i++) acc[i] = 0ull;

    int rA[2], kqA[2], sr[2];
    float4 pa[2], pb[2];
    #pragma unroll
    for (int i = 0; i < 2; i++) {
        int f = tid + i * 256;
        int rr = row0 + (f >> 2);
        rA[i] = (rr < NTOTc) ? rr : (NTOTc - 1);
        sr[i] = f >> 2;
        kqA[i] = (f & 3) * 4;
        pa[i] = *(const float4*)(A + (size_t)rA[i] * 128 + kqA[i]);
    }
    int kB = tid >> 4;
    int nB = (tid & 15) * 8;
    pb[0] = *(const float4*)(W + (size_t)kB * Nout + col0 + nB);
    pb[1] = *(const float4*)(W + (size_t)kB * Nout + col0 + nB + 4);

    #pragma unroll
    for (int i = 0; i < 2; i++) {
        As[0][kqA[i] + 0][sr[i]] = pa[i].x;
        As[0][kqA[i] + 1][sr[i]] = pa[i].y;
        As[0][kqA[i] + 2][sr[i]] = pa[i].z;
        As[0][kqA[i] + 3][sr[i]] = pa[i].w;
    }
    *(float4*)&Bs[0][kB][nB]     = pb[0];
    *(float4*)&Bs[0][kB][nB + 4] = pb[1];
    __syncthreads();

    #pragma unroll
    for (int kc = 0; kc < 8; kc++) {
        int cur = kc & 1;
        int nxt = cur ^ 1;
        if (kc < 7) {
            int k0n = (kc + 1) * 16;
            #pragma unroll
            for (int i = 0; i < 2; i++)
                pa[i] = *(const float4*)(A + (size_t)rA[i] * 128 + k0n + kqA[i]);
            pb[0] = *(const float4*)(W + (size_t)(k0n + kB) * Nout + col0 + nB);
            pb[1] = *(const float4*)(W + (size_t)(k0n + kB) * Nout + col0 + nB + 4);
        }
        #pragma unroll
        for (int k = 0; k < 16; k++) {
            float4 a0 = *(const float4*)&As[cur][k][ty * 8];
            float4 a1 = *(const float4*)&As[cur][k][ty * 8 + 4];
            const ull* bp = (const ull*)&Bs[cur][k][tx * 8];
            ull b0 = bp[0], b1 = bp[1], b2 = bp[2], b3 = bp[3];
            ull ad[8];
            ad[0] = pack2(a0.x, a0.x); ad[1] = pack2(a0.y, a0.y);
            ad[2] = pack2(a0.z, a0.z); ad[3] = pack2(a0.w, a0.w);
            ad[4] = pack2(a1.x, a1.x); ad[5] = pack2(a1.y, a1.y);
            ad[6] = pack2(a1.z, a1.z); ad[7] = pack2(a1.w, a1.w);
            #pragma unroll
            for (int i = 0; i < 8; i++) {
                acc[i * 4 + 0] = fma2(ad[i], b0, acc[i * 4 + 0]);
                acc[i * 4 + 1] = fma2(ad[i], b1, acc[i * 4 + 1]);
                acc[i * 4 + 2] = fma2(ad[i], b2, acc[i * 4 + 2]);
                acc[i * 4 + 3] = fma2(ad[i], b3, acc[i * 4 + 3]);
            }
        }
        if (kc < 7) {
            #pragma unroll
            for (int i = 0; i < 2; i++) {
                As[nxt][kqA[i] + 0][sr[i]] = pa[i].x;
                As[nxt][kqA[i] + 1][sr[i]] = pa[i].y;
                As[nxt][kqA[i] + 2][sr[i]] = pa[i].z;
                As[nxt][kqA[i] + 3][sr[i]] = pa[i].w;
            }
            *(float4*)&Bs[nxt][kB][nB]     = pb[0];
            *(float4*)&Bs[nxt][kB][nB + 4] = pb[1];
        }
        __syncthreads();
    }
}

// ================= fused GEMM launch: qkv (0..947) | skip (948..1572) =================
__global__ __launch_bounds__(256, 2) void gemm_kernel(
    const float* __restrict__ A,
    const float* __restrict__ Wq, const float* __restrict__ bq,
    const float* __restrict__ Wk, const float* __restrict__ bk,
    const float* __restrict__ Wv, const float* __restrict__ bv,
    const float* __restrict__ Wsk, const float* __restrict__ bsk,
    float* __restrict__ C,
    const float* __restrict__ bng, const float* __restrict__ bnb,
    const float* __restrict__ bnm, const float* __restrict__ bnv)
{
    __shared__ __align__(16) float As[2][16][132];
    __shared__ __align__(16) float Bs[2][16][132];
    int tid = threadIdx.x;
    int tx = tid & 15;
    int ty = tid >> 4;
    int bid = blockIdx.x;

    if (bid < QKVB) {
        int z = bid / 316;
        int b2 = bid - z * 316;
        int row0 = (b2 % 79) * 128;
        int col0 = (b2 / 79) * 128;
        const float* W = (z == 0) ? Wq : (z == 1) ? Wk : Wv;
        const float* bias = (z == 0) ? bq : (z == 1) ? bk : bv;

        ull acc[32];
        gemm_core(A, W, row0, col0, 512, acc, As, Bs);

        int gc = col0 + tx * 8;
        float bvv[8];
        #pragma unroll
        for (int j = 0; j < 8; j++) bvv[j] = bias[gc + j];

        #pragma unroll
        for (int i = 0; i < 8; i++) {
            int gr = row0 + ty * 8 + i;
            if (gr >= Nn) continue;
            float c[8];
            #pragma unroll
            for (int j = 0; j < 4; j++) {
                float2 p = unpack2(acc[i * 4 + j]);
                c[2 * j]     = p.x + bvv[2 * j];
                c[2 * j + 1] = p.y + bvv[2 * j + 1];
            }
            size_t o = (size_t)gr * 512 + gc;
            if (z == 0) {
                *(float4*)(g_q + o)     = make_float4(c[0], c[1], c[2], c[3]);
                *(float4*)(g_q + o + 4) = make_float4(c[4], c[5], c[6], c[7]);
            } else {
                __half2 h0 = __floats2half2_rn(c[0], c[1]);
                __half2 h1 = __floats2half2_rn(c[2], c[3]);
                __half2 h2 = __floats2half2_rn(c[4], c[5]);
                __half2 h3 = __floats2half2_rn(c[6], c[7]);
                uint4 pk = make_uint4(*(unsigned*)&h0, *(unsigned*)&h1,
                                      *(unsigned*)&h2, *(unsigned*)&h3);
                if (z == 1) *(uint4*)(g_kh + o) = pk;
                else        *(uint4*)(g_vh + o) = pk;
            }
        }
    } else {
        int row0 = (bid - QKVB) * 128;

        ull acc[32];
        gemm_core(A, Wsk, row0, 0, 128, acc, As, Bs);

        int gc = tx * 8;
        float bvv[8], scv[8], mnv[8], btv[8];
        #pragma unroll
        for (int j = 0; j < 8; j++) {
            bvv[j] = bsk[gc + j];
            scv[j] = bng[gc + j] * rsqrtf(bnv[gc + j] + 1e-5f);
            mnv[j] = bnm[gc + j];
            btv[j] = bnb[gc + j];
        }

        #pragma unroll
        for (int i = 0; i < 8; i++) {
            int gr = row0 + ty * 8 + i;
            float c[8];
            #pragma unroll
            for (int j = 0; j < 4; j++) {
                float2 p = unpack2(acc[i * 4 + j]);
                c[2 * j]     = p.x + bvv[2 * j];
                c[2 * j + 1] = p.y + bvv[2 * j + 1];
            }
            if (gr >= Nn) {
                #pragma unroll
                for (int j = 0; j < 8; j++)
                    c[j] = fmaxf((c[j] - mnv[j]) * scv[j] + btv[j], 0.f);
            }
            float* dstp = C + (size_t)gr * 128 + gc;
            *(float4*)(dstp)     = make_float4(c[0], c[1], c[2], c[3]);
            *(float4*)(dstp + 4) = make_float4(c[4], c[5], c[6], c[7]);
        }
    }
}

// ================= fused attention (fp16 K/V, 2-way ILP online softmax) =================
__global__ __launch_bounds__(128) void attn_kernel(
    const float* __restrict__ q, const __half* __restrict__ kh,
    const __half* __restrict__ vh, float* __restrict__ hnext,
    const float* __restrict__ bng, const float* __restrict__ bnb,
    const float* __restrict__ bnm, const float* __restrict__ bnv)
{
    int n = blockIdx.x;
    int warp = threadIdx.x >> 5;
    int lane = threadIdx.x & 31;
    __shared__ float outsh[4][128];

    const float4 qr = *(const float4*)(q + (size_t)n * 512 + warp * 128 + lane * 4);
    int b = g_off[n], e = g_off[n + 1];

    float m1 = -1e30f, d1 = 0.f, x10 = 0.f, x11 = 0.f, x12 = 0.f, x13 = 0.f;
    float m2 = -1e30f, d2 = 0.f, x20 = 0.f, x21 = 0.f, x22 = 0.f, x23 = 0.f;

    int ei = b;
    for (; ei + 1 < e; ei += 2) {
        int s1 = g_srcs[ei];
        int s2 = g_srcs[ei + 1];
        size_t base1 = (size_t)s1 * 512 + warp * 128;
        size_t base2 = (size_t)s2 * 512 + warp * 128;
        uint2 kr1 = ((const uint2*)(kh + base1))[lane];
        uint2 kr2 = ((const uint2*)(kh + base2))[lane];
        float2 ka1 = __half22float2(*(const __half2*)&kr1.x);
        float2 kb1 = __half22float2(*(const __half2*)&kr1.y);
        float2 ka2 = __half22float2(*(const __half2*)&kr2.x);
        float2 kb2 = __half22float2(*(const __half2*)&kr2.y);
        float p1 = qr.x * ka1.x + qr.y * ka1.y + qr.z * kb1.x + qr.w * kb1.y;
        float p2 = qr.x * ka2.x + qr.y * ka2.y + qr.z * kb2.x + qr.w * kb2.y;
        #pragma unroll
        for (int o = 16; o; o >>= 1) {
            p1 += __shfl_xor_sync(0xffffffffu, p1, o);
            p2 += __shfl_xor_sync(0xffffffffu, p2, o);
        }
        uint2 vr1 = ((const uint2*)(vh + base1))[lane];
        uint2 vr2 = ((const uint2*)(vh + base2))[lane];
        float a1 = p1 * 0.08838834764831843f;
        float a2 = p2 * 0.08838834764831843f;
        {
            float mn = fmaxf(m1, a1);
            float sc = __expf(m1 - mn);
            float w  = __expf(a1 - mn);
            float2 va = __half22float2(*(const __half2*)&vr1.x);
            float2 vb = __half22float2(*(const __half2*)&vr1.y);
            d1  = d1 * sc + w;
            x10 = x10 * sc + w * va.x;
            x11 = x11 * sc + w * va.y;
            x12 = x12 * sc + w * vb.x;
            x13 = x13 * sc + w * vb.y;
            m1 = mn;
        }
        {
            float mn = fmaxf(m2, a2);
            float sc = __expf(m2 - mn);
            float w  = __expf(a2 - mn);
            float2 va = __half22float2(*(const __half2*)&vr2.x);
            float2 vb = __half22float2(*(const __half2*)&vr2.y);
            d2  = d2 * sc + w;
            x20 = x20 * sc + w * va.x;
            x21 = x21 * sc + w * va.y;
            x22 = x22 * sc + w * vb.x;
            x23 = x23 * sc + w * vb.y;
            m2 = mn;
        }
    }
    if (ei < e) {
        int s = g_srcs[ei];
        size_t base = (size_t)s * 512 + warp * 128;
        uint2 kr = ((const uint2*)(kh + base))[lane];
        float2 ka = __half22float2(*(const __half2*)&kr.x);
        float2 kb = __half22float2(*(const __half2*)&kr.y);
        float p = qr.x * ka.x + qr.y * ka.y + qr.z * kb.x + qr.w * kb.y;
        #pragma unroll
        for (int o = 16; o; o >>= 1) p += __shfl_xor_sync(0xffffffffu, p, o);
        float a = p * 0.08838834764831843f;
        float mn = fmaxf(m1, a);
        float sc = __expf(m1 - mn);
        float w  = __expf(a - mn);
        uint2 vr = ((const uint2*)(vh + base))[lane];
        float2 va = __half22float2(*(const __half2*)&vr.x);
        float2 vb = __half22float2(*(const __half2*)&vr.y);
        d1  = d1 * sc + w;
        x10 = x10 * sc + w * va.x;
        x11 = x11 * sc + w * va.y;
        x12 = x12 * sc + w * vb.x;
        x13 = x13 * sc + w * vb.y;
        m1 = mn;
    }
    {
        float mn = fmaxf(m1, m2);
        float s1 = __expf(m1 - mn);
        float s2 = (d2 > 0.f) ? __expf(m2 - mn) : 0.f;
        d1  = d1 * s1 + d2 * s2;
        x10 = x10 * s1 + x20 * s2;
        x11 = x11 * s1 + x21 * s2;
        x12 = x12 * s1 + x22 * s2;
        x13 = x13 * s1 + x23 * s2;
    }
    float inv = 1.f / (d1 + 1e-16f);
    outsh[warp][lane * 4 + 0] = x10 * inv;
    outsh[warp][lane * 4 + 1] = x11 * inv;
    outsh[warp][lane * 4 + 2] = x12 * inv;
    outsh[warp][lane * 4 + 3] = x13 * inv;
    __syncthreads();

    int t = threadIdx.x;
    float val = hnext[(size_t)n * 128 + t] +
                0.25f * (outsh[0][t] + outsh[1][t] + outsh[2][t] + outsh[3][t]);
    float sc = bng[t] * rsqrtf(bnv[t] + 1e-5f);
    float r = (val - bnm[t]) * sc + bnb[t];
    hnext[(size_t)n * 128 + t] = fmaxf(r, 0.f);
}

// ================= two-stage sort-pool (warp-shuffle reductions) =================
__global__ __launch_bounds__(256) void sp1_kernel(const float* __restrict__ h)
{
    int g = blockIdx.x / 10;
    int part = blockIdx.x % 10;
    int t = threadIdx.x;
    int lane = t & 31, warp = t >> 5;
    __shared__ unsigned int skey[1000];
    __shared__ ull wbest[8];

    for (int i = t; i < 1000; i += 256) {
        float val = h[((size_t)g * Nn + part * 1000 + i) * 128 + 127];
        unsigned int bits = __float_as_uint(val);
        skey[i] = (bits & 0x80000000u) ? ~bits : (bits | 0x80000000u);
    }
    __syncthreads();

    for (int kk = 0; kk < Kk; kk++) {
        ull best = 0ull;
        for (int i = t; i < 1000; i += 256) {
            ull key = ((ull)skey[i] << 32) |
                      (unsigned int)(0xFFFFFFFFu - (part * 1000 + i));
            best = maxu64(best, key);
        }
        #pragma unroll
        for (int o = 16; o; o >>= 1)
            best = maxu64(best, __shfl_xor_sync(0xffffffffu, best, o));
        if (lane == 0) wbest[warp] = best;
        __syncthreads();
        if (t == 0) {
            ull top = wbest[0];
            #pragma unroll
            for (int w = 1; w < 8; w++) top = maxu64(top, wbest[w]);
            int nig = (int)(0xFFFFFFFFu - (unsigned int)(top & 0xFFFFFFFFull));
            g_cand[blockIdx.x * Kk + kk] = top;
            skey[nig - part * 1000] = 0;
        }
        __syncthreads();
    }
}

__global__ __launch_bounds__(256) void sp2_kernel(const float* __restrict__ h,
                                                  const float* __restrict__ age)
{
    int g = blockIdx.x;
    int t = threadIdx.x;
    int lane = t & 31, warp = t >> 5;
    __shared__ ull cand[300];
    __shared__ ull wbest[8];
    __shared__ ull s_top;

    for (int i = t; i < 300; i += 256) cand[i] = g_cand[g * 300 + i];
    __syncthreads();

    for (int kk = 0; kk < Kk; kk++) {
        ull best = 0ull;
        for (int i = t; i < 300; i += 256) best = maxu64(best, cand[i]);
        #pragma unroll
        for (int o = 16; o; o >>= 1)
            best = maxu64(best, __shfl_xor_sync(0xffffffffu, best, o));
        if (lane == 0) wbest[warp] = best;
        __syncthreads();
        if (t == 0) {
            ull top = wbest[0];
            #pragma unroll
            for (int w = 1; w < 8; w++) top = maxu64(top, wbest[w]);
            s_top = top;
            int nig = (int)(0xFFFFFFFFu - (unsigned int)(top & 0xFFFFFFFFull));
            g_topk[g * Kk + kk] = nig;
        }
        __syncthreads();
        ull top = s_top;
        for (int i = t; i < 300; i += 256) if (cand[i] == top) cand[i] = 0;
        __syncthreads();
    }

    for (int i = t; i < Kk * 128; i += 256) {
        int kkk = i >> 7, c = i & 127;
        int n = g_topk[g * Kk + kkk];
        g_z[g * ZLEN + i] = h[((size_t)g * Nn + n) * 128 + c];
    }
    if (t == 0) g_z[g * ZLEN + Kk * 128] = age[g];
}

// ================= MLP stage 1: W1 read ONCE; partials per (kpart, graph, col) ========
__global__ __launch_bounds__(256) void mlp1_kernel(const float* __restrict__ W1)
{
    int seg = blockIdx.x;
    int kp  = blockIdx.y;
    int t = threadIdx.x;
    __shared__ float zs[Bg][481];
    __shared__ float red[4][64][8];

    int j0 = kp * 480;
    int j1 = (kp == 7) ? ZLEN : (j0 + 480);
    int len = j1 - j0;

    for (int i = t; i < Bg * len; i += 256) {
        int g = i / len, j = i % len;
        zs[g][j] = g_z[g * ZLEN + j0 + j];
    }
    __syncthreads();

    int u = t & 63;
    int p = t >> 6;
    int col = seg * 64 + u;
    int jb = p * (len >> 2);
    int je = (p == 3) ? len : (jb + (len >> 2));

    float acc[8];
    #pragma unroll
    for (int g = 0; g < 8; g++) acc[g] = 0.f;
    for (int j = jb; j < je; j++) {
        float w = W1[(size_t)(j0 + j) * 512 + col];
        #pragma unroll
        for (int g = 0; g < 8; g++) acc[g] += zs[g][j] * w;
    }
    #pragma unroll
    for (int g = 0; g < 8; g++) red[p][u][g] = acc[g];
    __syncthreads();

    {
        int uu = t & 63;
        int gpair = t >> 6;
        #pragma unroll
        for (int h = 0; h < 2; h++) {
            int g = gpair * 2 + h;
            float s = red[0][uu][g] + red[1][uu][g] + red[2][uu][g] + red[3][uu][g];
            g_hidp[(kp * Bg + g) * 512 + seg * 64 + uu] = s;
        }
    }
}

// ================= MLP stage 2: sum partials + bias + relu + logits ================
__global__ __launch_bounds__(512) void mlp2_kernel(
    const float* __restrict__ b1,
    const float* __restrict__ W2, const float* __restrict__ b2,
    float* __restrict__ out)
{
    int g = blockIdx.x;
    int t = threadIdx.x;
    __shared__ float red0[512];
    __shared__ float red1[512];

    float s = b1[t];
    #pragma unroll
    for (int kp = 0; kp < 8; kp++) s += g_hidp[(kp * Bg + g) * 512 + t];
    float hid = fmaxf(s, 0.f);

    red0[t] = hid * W2[t * 2 + 0];
    red1[t] = hid * W2[t * 2 + 1];
    __syncthreads();
    for (int st = 256; st > 0; st >>= 1) {
        if (t < st) { red0[t] += red0[t + st]; red1[t] += red1[t + st]; }
        __syncthreads();
    }
    if (t == 0) {
        float o0 = red0[0] + b2[0];
        float o1 = red1[0] + b2[1];
        float mx = fmaxf(o0, o1);
        float lse = mx + logf(expf(o0 - mx) + expf(o1 - mx));
        out[g * 2 + 0] = o0 - lse;
        out[g * 2 + 1] = o1 - lse;
    }
}

// ================= launch =================
extern "C" void kernel_launch(void* const* d_in, const int* in_sizes, int n_in,
                              void* d_out, int out_size)
{
    const float* x     = (const float*)d_in[0];
    const int*   eidx  = (const int*)  d_in[1];
    const float* age   = (const float*)d_in[2];
    const float* Wq    = (const float*)d_in[3];
    const float* bq    = (const float*)d_in[4];
    const float* Wk    = (const float*)d_in[5];
    const float* bk    = (const float*)d_in[6];
    const float* Wv    = (const float*)d_in[7];
    const float* bv    = (const float*)d_in[8];
    const float* Wsk   = (const float*)d_in[9];
    const float* bsk   = (const float*)d_in[10];
    const float* bn_g  = (const float*)d_in[11];
    const float* bn_b  = (const float*)d_in[12];
    const float* bn_m  = (const float*)d_in[13];
    const float* bn_v  = (const float*)d_in[14];
    const float* W1    = (const float*)d_in[15];
    const float* b1    = (const float*)d_in[16];
    const float* W2    = (const float*)d_in[17];
    const float* b2    = (const float*)d_in[18];
    float* out = (float*)d_out;

    int E = in_sizes[1] / 2;
    const int* src = eidx;
    const int* dst = eidx + E;

    float *q, *hA, *hB;
    __half *kh, *vh;
    int *degp;
    cudaGetSymbolAddress((void**)&q,  g_q);
    cudaGetSymbolAddress((void**)&kh, g_kh);
    cudaGetSymbolAddress((void**)&vh, g_vh);
    cudaGetSymbolAddress((void**)&hA, g_hA);
    cudaGetSymbolAddress((void**)&hB, g_hB);
    cudaGetSymbolAddress((void**)&degp, g_deg);

    // CSR build
    cudaMemsetAsync(degp, 0, (Nn + 1) * sizeof(int));
    hist_kernel<<<(E + 255) / 256, 256>>>(dst, E);
    scan_kernel<<<1, 1024>>>();
    scatter_kernel<<<(E + 255) / 256, 256>>>(src, dst, E);

    const float* hcur = x;
    float* hnext = hA;
    for (int l = 0; l < 3; l++) {
        gemm_kernel<<<GEMMB, 256>>>(hcur, Wq, bq, Wk, bk, Wv, bv, Wsk, bsk, hnext,
                                    bn_g + l * 128, bn_b + l * 128,
                                    bn_m + l * 128, bn_v + l * 128);
        attn_kernel<<<Nn, 128>>>(q, kh, vh, hnext,
                                 bn_g + l * 128, bn_b + l * 128,
                                 bn_m + l * 128, bn_v + l * 128);
        hcur = hnext;
        hnext = (hcur == hA) ? hB : hA;
    }

    sp1_kernel<<<80, 256>>>(hcur);
    sp2_kernel<<<Bg, 256>>>(hcur, age);
    mlp1_kernel<<<dim3(8, 8), 256>>>(W1);
    mlp2_kernel<<<Bg, 512>>>(b1, W2, b2, out);
}